// round 1
// baseline (speedup 1.0000x reference)
#include <cuda_runtime.h>
#include <math.h>

#define BB 2
#define SS 2048
#define EE 768
#define HH 12
#define HD 64
#define MROWS (BB*SS)          // 4096
#define NQKV (3*EE)            // 2304
#define LN_EPS 1e-5f

// ---------------- scratch (no allocations allowed) ----------------
__device__ float g_xn[MROWS*EE];        // layernorm output
__device__ float g_q [BB*HH*SS*HD];     // [b,h,s,d]
__device__ float g_k [BB*HH*SS*HD];
__device__ float g_v [BB*HH*SS*HD];
__device__ float g_o [MROWS*EE];        // attention output, [b,s,e]

// ---------------- LayerNorm: one block per row ----------------
__global__ void __launch_bounds__(256) ln_kernel(
    const float* __restrict__ x, const float* __restrict__ gamma,
    const float* __restrict__ beta, float* __restrict__ xn)
{
    int row = blockIdx.x;
    int tid = threadIdx.x;
    const float* xr = x + (size_t)row * EE;
    float v0 = xr[tid], v1 = xr[tid+256], v2 = xr[tid+512];
    float s  = v0 + v1 + v2;
    float s2 = v0*v0 + v1*v1 + v2*v2;
    #pragma unroll
    for (int o = 16; o; o >>= 1) {
        s  += __shfl_xor_sync(0xffffffffu, s,  o);
        s2 += __shfl_xor_sync(0xffffffffu, s2, o);
    }
    __shared__ float sh0[8], sh1[8];
    int w = tid >> 5, l = tid & 31;
    if (l == 0) { sh0[w] = s; sh1[w] = s2; }
    __syncthreads();
    if (tid < 32) {
        s  = (l < 8) ? sh0[l] : 0.f;
        s2 = (l < 8) ? sh1[l] : 0.f;
        #pragma unroll
        for (int o = 4; o; o >>= 1) {
            s  += __shfl_xor_sync(0xffffffffu, s,  o);
            s2 += __shfl_xor_sync(0xffffffffu, s2, o);
        }
        if (l == 0) { sh0[0] = s; sh1[0] = s2; }
    }
    __syncthreads();
    s = sh0[0]; s2 = sh1[0];
    float mu   = s * (1.0f / EE);
    float var  = s2 * (1.0f / EE) - mu * mu;
    float rstd = rsqrtf(var + LN_EPS);
    float* xo = xn + (size_t)row * EE;
    xo[tid]     = (v0 - mu) * rstd * gamma[tid]     + beta[tid];
    xo[tid+256] = (v1 - mu) * rstd * gamma[tid+256] + beta[tid+256];
    xo[tid+512] = (v2 - mu) * rstd * gamma[tid+512] + beta[tid+512];
}

// ---------------- GEMM: C[m,n] = sum_k A[m,k]*W[n,k] + bias[n] ----------------
// 64x64 tile, BK=32, 256 threads, 4x4 microtile.
// EPI==0: scatter into q/k/v [b,h,s,d].  EPI==1: write C row-major [M,N].
template<int EPI>
__global__ void __launch_bounds__(256) gemm_kernel(
    const float* __restrict__ A, const float* __restrict__ W,
    const float* __restrict__ bias, float* __restrict__ C,
    float* __restrict__ Cq, float* __restrict__ Ck, float* __restrict__ Cv,
    int N)
{
    __shared__ float As[32][68];
    __shared__ float Ws[32][68];
    int tid = threadIdx.x;
    int m0 = blockIdx.y * 64, n0 = blockIdx.x * 64;
    int lrow = tid >> 2;
    int kg   = (tid & 3) * 8;
    const float* Ag = A + (size_t)(m0 + lrow) * EE + kg;
    const float* Wg = W + (size_t)(n0 + lrow) * EE + kg;
    int r0 = (tid >> 4) * 4;
    int c0 = (tid & 15) * 4;
    float acc[4][4] = {};
    for (int k0 = 0; k0 < EE; k0 += 32) {
        float4 a0 = *(const float4*)(Ag + k0);
        float4 a1 = *(const float4*)(Ag + k0 + 4);
        float4 w0 = *(const float4*)(Wg + k0);
        float4 w1 = *(const float4*)(Wg + k0 + 4);
        __syncthreads();
        As[kg+0][lrow]=a0.x; As[kg+1][lrow]=a0.y; As[kg+2][lrow]=a0.z; As[kg+3][lrow]=a0.w;
        As[kg+4][lrow]=a1.x; As[kg+5][lrow]=a1.y; As[kg+6][lrow]=a1.z; As[kg+7][lrow]=a1.w;
        Ws[kg+0][lrow]=w0.x; Ws[kg+1][lrow]=w0.y; Ws[kg+2][lrow]=w0.z; Ws[kg+3][lrow]=w0.w;
        Ws[kg+4][lrow]=w1.x; Ws[kg+5][lrow]=w1.y; Ws[kg+6][lrow]=w1.z; Ws[kg+7][lrow]=w1.w;
        __syncthreads();
        #pragma unroll
        for (int kk = 0; kk < 32; kk++) {
            float4 a4 = *(const float4*)&As[kk][r0];
            float4 w4 = *(const float4*)&Ws[kk][c0];
            acc[0][0] += a4.x*w4.x; acc[0][1] += a4.x*w4.y; acc[0][2] += a4.x*w4.z; acc[0][3] += a4.x*w4.w;
            acc[1][0] += a4.y*w4.x; acc[1][1] += a4.y*w4.y; acc[1][2] += a4.y*w4.z; acc[1][3] += a4.y*w4.w;
            acc[2][0] += a4.z*w4.x; acc[2][1] += a4.z*w4.y; acc[2][2] += a4.z*w4.z; acc[2][3] += a4.z*w4.w;
            acc[3][0] += a4.w*w4.x; acc[3][1] += a4.w*w4.y; acc[3][2] += a4.w*w4.z; acc[3][3] += a4.w*w4.w;
        }
    }
    #pragma unroll
    for (int i = 0; i < 4; i++) {
        int m = m0 + r0 + i;
        #pragma unroll
        for (int j = 0; j < 4; j++) {
            int n = n0 + c0 + j;
            float val = acc[i][j] + bias[n];
            if (EPI == 0) {
                int b_ = m >> 11;           // m / S
                int s_ = m & 2047;          // m % S
                int h_ = n / 192;
                int rem = n - h_ * 192;
                int which = rem >> 6;
                int d_ = rem & 63;
                size_t idx = ((size_t)(b_ * HH + h_) * SS + s_) * HD + d_;
                if (which == 0)      Cq[idx] = val;
                else if (which == 1) Ck[idx] = val;
                else                 Cv[idx] = val;
            } else {
                C[(size_t)m * N + n] = val;
            }
        }
    }
}

// ---------------- Flash attention: BM=BN=64, HD=64, 256 threads ----------------
// grid: (S/64, B*H). Each thread owns (row r, 16 cols c0..c0+15); 4 threads/row.
#define ATTN_SMEM (3 * 64 * 68 * 4)
__global__ void __launch_bounds__(256, 2) attn_kernel(
    const float* __restrict__ Q, const float* __restrict__ K,
    const float* __restrict__ V, float* __restrict__ O)
{
    extern __shared__ float sm[];
    float* Qs = sm;              // Qs[r*68 + d]
    float* Kt = sm + 64*68;      // Kt[d*68 + c]  (transposed)
    float* Vs = sm + 2*64*68;    // Vs[c*68 + d]
    int tid = threadIdx.x;
    int bh  = blockIdx.y;
    int b_  = bh / HH;
    int h_  = bh - b_ * HH;
    int qt  = blockIdx.x;
    const float* Qg = Q + ((size_t)bh * SS + qt * 64) * HD;
    const float* Kg = K + (size_t)bh * SS * HD;
    const float* Vg = V + (size_t)bh * SS * HD;

    {   // load Q tile
        int r = tid >> 2, d0 = (tid & 3) * 16;
        const float4* src = (const float4*)(Qg + r * HD + d0);
        float4* dst = (float4*)&Qs[r * 68 + d0];
        dst[0] = src[0]; dst[1] = src[1]; dst[2] = src[2]; dst[3] = src[3];
    }

    const int r  = tid >> 2;
    const int c0 = (tid & 3) * 16;
    float Op[64];
    #pragma unroll
    for (int i = 0; i < 64; i++) Op[i] = 0.f;
    float m_i = -1e30f, l_i = 0.f;

    for (int kt = 0; kt < SS / 64; kt++) {
        __syncthreads();
        {   // stage K (transposed) and V
            int c = tid >> 2, d0 = (tid & 3) * 16;
            const float* kr = Kg + (size_t)(kt * 64 + c) * HD + d0;
            #pragma unroll
            for (int u = 0; u < 16; u++) Kt[(d0 + u) * 68 + c] = kr[u];
            const float4* vr = (const float4*)(Vg + (size_t)(kt * 64 + c) * HD + d0);
            float4* vd = (float4*)&Vs[c * 68 + d0];
            vd[0] = vr[0]; vd[1] = vr[1]; vd[2] = vr[2]; vd[3] = vr[3];
        }
        __syncthreads();

        float acc[16];
        #pragma unroll
        for (int j = 0; j < 16; j++) acc[j] = 0.f;
        #pragma unroll 16
        for (int d = 0; d < 64; d++) {
            float q = Qs[r * 68 + d];
            const float4* krow = (const float4*)&Kt[d * 68 + c0];
            float4 k0_ = krow[0], k1_ = krow[1], k2_ = krow[2], k3_ = krow[3];
            acc[0]  += q * k0_.x; acc[1]  += q * k0_.y; acc[2]  += q * k0_.z; acc[3]  += q * k0_.w;
            acc[4]  += q * k1_.x; acc[5]  += q * k1_.y; acc[6]  += q * k1_.z; acc[7]  += q * k1_.w;
            acc[8]  += q * k2_.x; acc[9]  += q * k2_.y; acc[10] += q * k2_.z; acc[11] += q * k2_.w;
            acc[12] += q * k3_.x; acc[13] += q * k3_.y; acc[14] += q * k3_.z; acc[15] += q * k3_.w;
        }
        const float sc = 0.125f;   // 1/sqrt(64)
        float tmax = acc[0];
        #pragma unroll
        for (int j = 1; j < 16; j++) tmax = fmaxf(tmax, acc[j]);
        tmax *= sc;
        tmax = fmaxf(tmax, __shfl_xor_sync(0xffffffffu, tmax, 1));
        tmax = fmaxf(tmax, __shfl_xor_sync(0xffffffffu, tmax, 2));
        float m_new = fmaxf(m_i, tmax);
        float psum = 0.f;
        #pragma unroll
        for (int j = 0; j < 16; j++) {
            float p = __expf(acc[j] * sc - m_new);
            acc[j] = p;
            psum += p;
        }
        psum += __shfl_xor_sync(0xffffffffu, psum, 1);
        psum += __shfl_xor_sync(0xffffffffu, psum, 2);
        float alpha = __expf(m_i - m_new);
        l_i = l_i * alpha + psum;
        m_i = m_new;
        #pragma unroll
        for (int dv = 0; dv < 64; dv++) Op[dv] *= alpha;
        #pragma unroll
        for (int j = 0; j < 16; j++) {
            float p = acc[j];
            const float4* vrow = (const float4*)&Vs[(c0 + j) * 68];
            #pragma unroll
            for (int dq = 0; dq < 16; dq++) {
                float4 v4 = vrow[dq];
                Op[dq*4+0] += p * v4.x; Op[dq*4+1] += p * v4.y;
                Op[dq*4+2] += p * v4.z; Op[dq*4+3] += p * v4.w;
            }
        }
    }

    // reduce partial O across the 4 threads of each row, normalize, store
    float inv = 1.0f / l_i;
    #pragma unroll
    for (int dv = 0; dv < 64; dv++) {
        float v = Op[dv];
        v += __shfl_xor_sync(0xffffffffu, v, 1);
        v += __shfl_xor_sync(0xffffffffu, v, 2);
        Op[dv] = v;
    }
    int s_ = qt * 64 + r;
    float* Og = O + ((size_t)(b_ * SS + s_)) * EE + h_ * HD;
    int q4 = tid & 3;
    #pragma unroll
    for (int u = 0; u < 16; u++) {
        int dv = q4 * 16 + u;
        Og[dv] = Op[dv] * inv;
    }
}

// ---------------- launch ----------------
extern "C" void kernel_launch(void* const* d_in, const int* in_sizes, int n_in,
                              void* d_out, int out_size)
{
    const float* x     = (const float*)d_in[0];
    const float* gamma = (const float*)d_in[1];
    const float* beta  = (const float*)d_in[2];
    const float* Wqkv  = (const float*)d_in[3];
    const float* bqkv  = (const float*)d_in[4];
    const float* Wo    = (const float*)d_in[5];
    const float* bo    = (const float*)d_in[6];
    float* out = (float*)d_out;

    float *xn, *q, *k, *v, *o;
    cudaGetSymbolAddress((void**)&xn, g_xn);
    cudaGetSymbolAddress((void**)&q,  g_q);
    cudaGetSymbolAddress((void**)&k,  g_k);
    cudaGetSymbolAddress((void**)&v,  g_v);
    cudaGetSymbolAddress((void**)&o,  g_o);

    cudaFuncSetAttribute(attn_kernel, cudaFuncAttributeMaxDynamicSharedMemorySize, ATTN_SMEM);

    ln_kernel<<<MROWS, 256>>>(x, gamma, beta, xn);
    gemm_kernel<0><<<dim3(NQKV/64, MROWS/64), 256>>>(xn, Wqkv, bqkv, nullptr, q, k, v, NQKV);
    attn_kernel<<<dim3(SS/64, BB*HH), 256, ATTN_SMEM>>>(q, k, v, o);
    gemm_kernel<1><<<dim3(EE/64, MROWS/64), 256>>>(o, Wo, bo, out, nullptr, nullptr, nullptr, EE);
}

// round 2
// speedup vs baseline: 4.1045x; 4.1045x over previous
#include <cuda_runtime.h>
#include <math.h>

#define BB 2
#define SS 2048
#define EE 768
#define HH 12
#define HD 64
#define MROWS (BB*SS)          // 4096
#define NQKV (3*EE)            // 2304
#define LN_EPS 1e-5f

// ---------------- scratch (no allocations allowed) ----------------
__device__ float g_xn[MROWS*EE];        // layernorm output
__device__ float g_q [BB*HH*SS*HD];     // [b,h,s,d]
__device__ float g_k [BB*HH*SS*HD];
__device__ float g_v [BB*HH*SS*HD];
__device__ float g_o [MROWS*EE];        // attention output, [b,s,e]

// ---------------- LayerNorm: one block per row ----------------
__global__ void __launch_bounds__(256) ln_kernel(
    const float* __restrict__ x, const float* __restrict__ gamma,
    const float* __restrict__ beta, float* __restrict__ xn)
{
    int row = blockIdx.x;
    int tid = threadIdx.x;
    const float* xr = x + (size_t)row * EE;
    float v0 = xr[tid], v1 = xr[tid+256], v2 = xr[tid+512];
    float s  = v0 + v1 + v2;
    float s2 = v0*v0 + v1*v1 + v2*v2;
    #pragma unroll
    for (int o = 16; o; o >>= 1) {
        s  += __shfl_xor_sync(0xffffffffu, s,  o);
        s2 += __shfl_xor_sync(0xffffffffu, s2, o);
    }
    __shared__ float sh0[8], sh1[8];
    int w = tid >> 5, l = tid & 31;
    if (l == 0) { sh0[w] = s; sh1[w] = s2; }
    __syncthreads();
    if (tid < 32) {
        s  = (l < 8) ? sh0[l] : 0.f;
        s2 = (l < 8) ? sh1[l] : 0.f;
        #pragma unroll
        for (int o = 4; o; o >>= 1) {
            s  += __shfl_xor_sync(0xffffffffu, s,  o);
            s2 += __shfl_xor_sync(0xffffffffu, s2, o);
        }
        if (l == 0) { sh0[0] = s; sh1[0] = s2; }
    }
    __syncthreads();
    s = sh0[0]; s2 = sh1[0];
    float mu   = s * (1.0f / EE);
    float var  = s2 * (1.0f / EE) - mu * mu;
    float rstd = rsqrtf(var + LN_EPS);
    float* xo = xn + (size_t)row * EE;
    xo[tid]     = (v0 - mu) * rstd * gamma[tid]     + beta[tid];
    xo[tid+256] = (v1 - mu) * rstd * gamma[tid+256] + beta[tid+256];
    xo[tid+512] = (v2 - mu) * rstd * gamma[tid+512] + beta[tid+512];
}

// ---------------- GEMM: C[m,n] = sum_k A[m,k]*W[n,k] + bias[n] ----------------
// 128x64 tile, BK=32, 256 threads, 8x4 microtile.
// EPI==0: scatter into q/k/v [b,h,s,d].  EPI==1: write C row-major [M,N].
template<int EPI>
__global__ void __launch_bounds__(256) gemm_kernel(
    const float* __restrict__ A, const float* __restrict__ W,
    const float* __restrict__ bias, float* __restrict__ C,
    float* __restrict__ Cq, float* __restrict__ Ck, float* __restrict__ Cv,
    int N)
{
    __shared__ float As[32][132];   // [k][m], padded
    __shared__ float Ws[32][68];    // [k][n], padded
    int tid = threadIdx.x;
    int m0 = blockIdx.y * 128, n0 = blockIdx.x * 64;

    int alr = tid >> 1;             // 0..127  (A row within tile)
    int akg = (tid & 1) * 16;       // k offset 0/16
    const float* Ag = A + (size_t)(m0 + alr) * EE + akg;
    int wlr = tid >> 2;             // 0..63   (W row within tile)
    int wkg = (tid & 3) * 8;        // k offset
    const float* Wg = W + (size_t)(n0 + wlr) * EE + wkg;

    int ty = tid >> 4, tx = tid & 15;
    int r0 = ty * 8, c0 = tx * 4;
    float acc[8][4] = {};

    for (int k0 = 0; k0 < EE; k0 += 32) {
        float4 a0 = *(const float4*)(Ag + k0);
        float4 a1 = *(const float4*)(Ag + k0 + 4);
        float4 a2 = *(const float4*)(Ag + k0 + 8);
        float4 a3 = *(const float4*)(Ag + k0 + 12);
        float4 w0 = *(const float4*)(Wg + k0);
        float4 w1 = *(const float4*)(Wg + k0 + 4);
        __syncthreads();
        As[akg+ 0][alr]=a0.x; As[akg+ 1][alr]=a0.y; As[akg+ 2][alr]=a0.z; As[akg+ 3][alr]=a0.w;
        As[akg+ 4][alr]=a1.x; As[akg+ 5][alr]=a1.y; As[akg+ 6][alr]=a1.z; As[akg+ 7][alr]=a1.w;
        As[akg+ 8][alr]=a2.x; As[akg+ 9][alr]=a2.y; As[akg+10][alr]=a2.z; As[akg+11][alr]=a2.w;
        As[akg+12][alr]=a3.x; As[akg+13][alr]=a3.y; As[akg+14][alr]=a3.z; As[akg+15][alr]=a3.w;
        Ws[wkg+0][wlr]=w0.x; Ws[wkg+1][wlr]=w0.y; Ws[wkg+2][wlr]=w0.z; Ws[wkg+3][wlr]=w0.w;
        Ws[wkg+4][wlr]=w1.x; Ws[wkg+5][wlr]=w1.y; Ws[wkg+6][wlr]=w1.z; Ws[wkg+7][wlr]=w1.w;
        __syncthreads();
        #pragma unroll
        for (int kk = 0; kk < 32; kk++) {
            float4 x0 = *(const float4*)&As[kk][r0];
            float4 x1 = *(const float4*)&As[kk][r0+4];
            float4 b0 = *(const float4*)&Ws[kk][c0];
            acc[0][0]+=x0.x*b0.x; acc[0][1]+=x0.x*b0.y; acc[0][2]+=x0.x*b0.z; acc[0][3]+=x0.x*b0.w;
            acc[1][0]+=x0.y*b0.x; acc[1][1]+=x0.y*b0.y; acc[1][2]+=x0.y*b0.z; acc[1][3]+=x0.y*b0.w;
            acc[2][0]+=x0.z*b0.x; acc[2][1]+=x0.z*b0.y; acc[2][2]+=x0.z*b0.z; acc[2][3]+=x0.z*b0.w;
            acc[3][0]+=x0.w*b0.x; acc[3][1]+=x0.w*b0.y; acc[3][2]+=x0.w*b0.z; acc[3][3]+=x0.w*b0.w;
            acc[4][0]+=x1.x*b0.x; acc[4][1]+=x1.x*b0.y; acc[4][2]+=x1.x*b0.z; acc[4][3]+=x1.x*b0.w;
            acc[5][0]+=x1.y*b0.x; acc[5][1]+=x1.y*b0.y; acc[5][2]+=x1.y*b0.z; acc[5][3]+=x1.y*b0.w;
            acc[6][0]+=x1.z*b0.x; acc[6][1]+=x1.z*b0.y; acc[6][2]+=x1.z*b0.z; acc[6][3]+=x1.z*b0.w;
            acc[7][0]+=x1.w*b0.x; acc[7][1]+=x1.w*b0.y; acc[7][2]+=x1.w*b0.z; acc[7][3]+=x1.w*b0.w;
        }
    }

    if (EPI == 1) {
        float4 b4 = *(const float4*)&bias[n0 + c0];
        #pragma unroll
        for (int i = 0; i < 8; i++) {
            int m = m0 + r0 + i;
            float4 o4;
            o4.x = acc[i][0] + b4.x; o4.y = acc[i][1] + b4.y;
            o4.z = acc[i][2] + b4.z; o4.w = acc[i][3] + b4.w;
            *(float4*)&C[(size_t)m * N + n0 + c0] = o4;
        }
    } else {
        #pragma unroll
        for (int i = 0; i < 8; i++) {
            int m = m0 + r0 + i;
            int b_ = m >> 11;           // m / S
            int s_ = m & 2047;          // m % S
            #pragma unroll
            for (int j = 0; j < 4; j++) {
                int n = n0 + c0 + j;
                float val = acc[i][j] + bias[n];
                int h_ = n / 192;
                int rem = n - h_ * 192;
                int which = rem >> 6;
                int d_ = rem & 63;
                size_t idx = ((size_t)(b_ * HH + h_) * SS + s_) * HD + d_;
                if (which == 0)      Cq[idx] = val;
                else if (which == 1) Ck[idx] = val;
                else                 Cv[idx] = val;
            }
        }
    }
}

// ---------------- Flash attention v2: BM=BN=64, HD=64, 256 threads ----------------
// 16x16 thread grid; 4x4 microtile for both S=QK^T and O+=P*V (all in registers).
#define ATTN_SMEM (4 * 64 * 68 * 4)
__global__ void __launch_bounds__(256, 2) attn_kernel(
    const float* __restrict__ Q, const float* __restrict__ K,
    const float* __restrict__ V, float* __restrict__ O)
{
    extern __shared__ float sm[];
    float* Qt = sm;              // [d][r]  (transposed)
    float* Kt = sm + 64*68;      // [d][c]  (transposed)
    float* Vs = sm + 2*64*68;    // [c][d]
    float* Pt = sm + 3*64*68;    // [c][r]  (transposed P)
    int tid = threadIdx.x;
    int bh  = blockIdx.y;
    int b_  = bh / HH;
    int h_  = bh - b_ * HH;
    const float* Qg = Q + ((size_t)bh * SS + blockIdx.x * 64) * HD;
    const float* Kg = K + (size_t)bh * SS * HD;
    const float* Vg = V + (size_t)bh * SS * HD;

    int lr  = tid >> 2;          // 0..63 (load row)
    int ld0 = (tid & 3) * 16;    // load d offset

    {   // load Q tile transposed
        float4 t0 = *(const float4*)(Qg + lr * HD + ld0);
        float4 t1 = *(const float4*)(Qg + lr * HD + ld0 + 4);
        float4 t2 = *(const float4*)(Qg + lr * HD + ld0 + 8);
        float4 t3 = *(const float4*)(Qg + lr * HD + ld0 + 12);
        Qt[(ld0+ 0)*68+lr]=t0.x; Qt[(ld0+ 1)*68+lr]=t0.y; Qt[(ld0+ 2)*68+lr]=t0.z; Qt[(ld0+ 3)*68+lr]=t0.w;
        Qt[(ld0+ 4)*68+lr]=t1.x; Qt[(ld0+ 5)*68+lr]=t1.y; Qt[(ld0+ 6)*68+lr]=t1.z; Qt[(ld0+ 7)*68+lr]=t1.w;
        Qt[(ld0+ 8)*68+lr]=t2.x; Qt[(ld0+ 9)*68+lr]=t2.y; Qt[(ld0+10)*68+lr]=t2.z; Qt[(ld0+11)*68+lr]=t2.w;
        Qt[(ld0+12)*68+lr]=t3.x; Qt[(ld0+13)*68+lr]=t3.y; Qt[(ld0+14)*68+lr]=t3.z; Qt[(ld0+15)*68+lr]=t3.w;
    }

    int ty = tid >> 4, tx = tid & 15;
    int r0 = ty * 4, c0 = tx * 4;
    float Oa[4][4] = {};
    float m_i[4], l_i[4];
    #pragma unroll
    for (int i = 0; i < 4; i++) { m_i[i] = -1e30f; l_i[i] = 0.f; }

    for (int kt = 0; kt < SS / 64; kt++) {
        __syncthreads();
        {   // stage K (transposed) and V (direct)
            const float* kr = Kg + (size_t)(kt * 64 + lr) * HD + ld0;
            float4 t0 = *(const float4*)(kr);
            float4 t1 = *(const float4*)(kr + 4);
            float4 t2 = *(const float4*)(kr + 8);
            float4 t3 = *(const float4*)(kr + 12);
            Kt[(ld0+ 0)*68+lr]=t0.x; Kt[(ld0+ 1)*68+lr]=t0.y; Kt[(ld0+ 2)*68+lr]=t0.z; Kt[(ld0+ 3)*68+lr]=t0.w;
            Kt[(ld0+ 4)*68+lr]=t1.x; Kt[(ld0+ 5)*68+lr]=t1.y; Kt[(ld0+ 6)*68+lr]=t1.z; Kt[(ld0+ 7)*68+lr]=t1.w;
            Kt[(ld0+ 8)*68+lr]=t2.x; Kt[(ld0+ 9)*68+lr]=t2.y; Kt[(ld0+10)*68+lr]=t2.z; Kt[(ld0+11)*68+lr]=t2.w;
            Kt[(ld0+12)*68+lr]=t3.x; Kt[(ld0+13)*68+lr]=t3.y; Kt[(ld0+14)*68+lr]=t3.z; Kt[(ld0+15)*68+lr]=t3.w;
            const float4* vr = (const float4*)(Vg + (size_t)(kt * 64 + lr) * HD + ld0);
            float4* vd = (float4*)&Vs[lr * 68 + ld0];
            vd[0] = vr[0]; vd[1] = vr[1]; vd[2] = vr[2]; vd[3] = vr[3];
        }
        __syncthreads();

        // S = Q @ K^T  (4x4 microtile)
        float s[4][4] = {};
        #pragma unroll
        for (int d = 0; d < 64; d++) {
            float4 q4 = *(const float4*)&Qt[d * 68 + r0];
            float4 k4 = *(const float4*)&Kt[d * 68 + c0];
            s[0][0]+=q4.x*k4.x; s[0][1]+=q4.x*k4.y; s[0][2]+=q4.x*k4.z; s[0][3]+=q4.x*k4.w;
            s[1][0]+=q4.y*k4.x; s[1][1]+=q4.y*k4.y; s[1][2]+=q4.y*k4.z; s[1][3]+=q4.y*k4.w;
            s[2][0]+=q4.z*k4.x; s[2][1]+=q4.z*k4.y; s[2][2]+=q4.z*k4.z; s[2][3]+=q4.z*k4.w;
            s[3][0]+=q4.w*k4.x; s[3][1]+=q4.w*k4.y; s[3][2]+=q4.w*k4.z; s[3][3]+=q4.w*k4.w;
        }

        // online softmax over rows (reduce across 16 tx-lanes; tx = low 4 lane bits)
        const float sc = 0.125f;   // 1/sqrt(64)
        #pragma unroll
        for (int i = 0; i < 4; i++) {
            float rm = fmaxf(fmaxf(s[i][0], s[i][1]), fmaxf(s[i][2], s[i][3])) * sc;
            rm = fmaxf(rm, __shfl_xor_sync(0xffffffffu, rm, 1));
            rm = fmaxf(rm, __shfl_xor_sync(0xffffffffu, rm, 2));
            rm = fmaxf(rm, __shfl_xor_sync(0xffffffffu, rm, 4));
            rm = fmaxf(rm, __shfl_xor_sync(0xffffffffu, rm, 8));
            float mn = fmaxf(m_i[i], rm);
            float rs = 0.f;
            #pragma unroll
            for (int j = 0; j < 4; j++) {
                float p = __expf(s[i][j] * sc - mn);
                s[i][j] = p;
                rs += p;
            }
            rs += __shfl_xor_sync(0xffffffffu, rs, 1);
            rs += __shfl_xor_sync(0xffffffffu, rs, 2);
            rs += __shfl_xor_sync(0xffffffffu, rs, 4);
            rs += __shfl_xor_sync(0xffffffffu, rs, 8);
            float alpha = __expf(m_i[i] - mn);
            l_i[i] = l_i[i] * alpha + rs;
            m_i[i] = mn;
            #pragma unroll
            for (int j = 0; j < 4; j++) Oa[i][j] *= alpha;
        }

        // write P transposed to smem
        #pragma unroll
        for (int i = 0; i < 4; i++)
            #pragma unroll
            for (int j = 0; j < 4; j++)
                Pt[(c0 + j) * 68 + r0 + i] = s[i][j];
        __syncthreads();

        // O += P @ V (4x4 microtile over d-cols c0..c0+3)
        #pragma unroll
        for (int kk = 0; kk < 64; kk++) {
            float4 p4 = *(const float4*)&Pt[kk * 68 + r0];
            float4 v4 = *(const float4*)&Vs[kk * 68 + c0];
            Oa[0][0]+=p4.x*v4.x; Oa[0][1]+=p4.x*v4.y; Oa[0][2]+=p4.x*v4.z; Oa[0][3]+=p4.x*v4.w;
            Oa[1][0]+=p4.y*v4.x; Oa[1][1]+=p4.y*v4.y; Oa[1][2]+=p4.y*v4.z; Oa[1][3]+=p4.y*v4.w;
            Oa[2][0]+=p4.z*v4.x; Oa[2][1]+=p4.z*v4.y; Oa[2][2]+=p4.z*v4.z; Oa[2][3]+=p4.z*v4.w;
            Oa[3][0]+=p4.w*v4.x; Oa[3][1]+=p4.w*v4.y; Oa[3][2]+=p4.w*v4.z; Oa[3][3]+=p4.w*v4.w;
        }
    }

    // normalize and store: O row = (b, s0+r0+i), col = h*64 + c0..c0+3
    int s_base = blockIdx.x * 64 + r0;
    #pragma unroll
    for (int i = 0; i < 4; i++) {
        float inv = 1.0f / l_i[i];
        float4 o4;
        o4.x = Oa[i][0]*inv; o4.y = Oa[i][1]*inv; o4.z = Oa[i][2]*inv; o4.w = Oa[i][3]*inv;
        *(float4*)&O[((size_t)(b_ * SS + s_base + i)) * EE + h_ * HD + c0] = o4;
    }
}

// ---------------- launch ----------------
extern "C" void kernel_launch(void* const* d_in, const int* in_sizes, int n_in,
                              void* d_out, int out_size)
{
    const float* x     = (const float*)d_in[0];
    const float* gamma = (const float*)d_in[1];
    const float* beta  = (const float*)d_in[2];
    const float* Wqkv  = (const float*)d_in[3];
    const float* bqkv  = (const float*)d_in[4];
    const float* Wo    = (const float*)d_in[5];
    const float* bo    = (const float*)d_in[6];
    float* out = (float*)d_out;

    float *xn, *q, *k, *v, *o;
    cudaGetSymbolAddress((void**)&xn, g_xn);
    cudaGetSymbolAddress((void**)&q,  g_q);
    cudaGetSymbolAddress((void**)&k,  g_k);
    cudaGetSymbolAddress((void**)&v,  g_v);
    cudaGetSymbolAddress((void**)&o,  g_o);

    cudaFuncSetAttribute(attn_kernel, cudaFuncAttributeMaxDynamicSharedMemorySize, ATTN_SMEM);

    ln_kernel<<<MROWS, 256>>>(x, gamma, beta, xn);
    gemm_kernel<0><<<dim3(NQKV/64, MROWS/128), 256>>>(xn, Wqkv, bqkv, nullptr, q, k, v, NQKV);
    attn_kernel<<<dim3(SS/64, BB*HH), 256, ATTN_SMEM>>>(q, k, v, o);
    gemm_kernel<1><<<dim3(EE/64, MROWS/128), 256>>>(o, Wo, bo, out, nullptr, nullptr, nullptr, EE);
}

// round 4
// speedup vs baseline: 4.9989x; 1.2179x over previous
#include <cuda_runtime.h>
#include <cuda_bf16.h>
#include <math.h>
#include <cstdint>

#define BB 2
#define SS 2048
#define EE 768
#define HH 12
#define HD 64
#define MROWS (BB*SS)          // 4096
#define NQKV (3*EE)            // 2304
#define LN_EPS 1e-5f

// ---------------- scratch (no allocations allowed) ----------------
__device__ __align__(16) __nv_bfloat16 g_xh[MROWS*EE];    // LN out hi
__device__ __align__(16) __nv_bfloat16 g_xl[MROWS*EE];    // LN out lo
__device__ __align__(16) __nv_bfloat16 g_wqh[NQKV*EE];    // Wqkv hi
__device__ __align__(16) __nv_bfloat16 g_wql[NQKV*EE];    // Wqkv lo
__device__ __align__(16) __nv_bfloat16 g_woh[EE*EE];      // Wo hi
__device__ __align__(16) __nv_bfloat16 g_wol[EE*EE];      // Wo lo
__device__ float g_q [BB*HH*SS*HD];     // [b,h,s,d]
__device__ float g_k [BB*HH*SS*HD];
__device__ float g_v [BB*HH*SS*HD];
__device__ __align__(16) __nv_bfloat16 g_oh[MROWS*EE];    // attn out hi
__device__ __align__(16) __nv_bfloat16 g_ol[MROWS*EE];    // attn out lo

// ---------------- LayerNorm: one block per row, emits bf16 hi/lo planes ----------------
__global__ void __launch_bounds__(256) ln_kernel(
    const float* __restrict__ x, const float* __restrict__ gamma,
    const float* __restrict__ beta, __nv_bfloat16* __restrict__ xh,
    __nv_bfloat16* __restrict__ xl)
{
    int row = blockIdx.x;
    int tid = threadIdx.x;
    const float* xr = x + (size_t)row * EE;
    float v0 = xr[tid], v1 = xr[tid+256], v2 = xr[tid+512];
    float s  = v0 + v1 + v2;
    float s2 = v0*v0 + v1*v1 + v2*v2;
    #pragma unroll
    for (int o = 16; o; o >>= 1) {
        s  += __shfl_xor_sync(0xffffffffu, s,  o);
        s2 += __shfl_xor_sync(0xffffffffu, s2, o);
    }
    __shared__ float sh0[8], sh1[8];
    int w = tid >> 5, l = tid & 31;
    if (l == 0) { sh0[w] = s; sh1[w] = s2; }
    __syncthreads();
    if (tid < 32) {
        s  = (l < 8) ? sh0[l] : 0.f;
        s2 = (l < 8) ? sh1[l] : 0.f;
        #pragma unroll
        for (int o = 4; o; o >>= 1) {
            s  += __shfl_xor_sync(0xffffffffu, s,  o);
            s2 += __shfl_xor_sync(0xffffffffu, s2, o);
        }
        if (l == 0) { sh0[0] = s; sh1[0] = s2; }
    }
    __syncthreads();
    s = sh0[0]; s2 = sh1[0];
    float mu   = s * (1.0f / EE);
    float var  = s2 * (1.0f / EE) - mu * mu;
    float rstd = rsqrtf(var + LN_EPS);
    size_t base = (size_t)row * EE;
    #pragma unroll
    for (int p = 0; p < 3; p++) {
        int c = tid + p * 256;
        float v = (p == 0) ? v0 : (p == 1) ? v1 : v2;
        float y = (v - mu) * rstd * gamma[c] + beta[c];
        __nv_bfloat16 h = __float2bfloat16(y);
        xh[base + c] = h;
        xl[base + c] = __float2bfloat16(y - __bfloat162float(h));
    }
}

// ---------------- fp32 -> bf16 hi/lo split ----------------
__global__ void __launch_bounds__(256) cvt_kernel(
    const float* __restrict__ w, __nv_bfloat16* __restrict__ hi,
    __nv_bfloat16* __restrict__ lo, int n)
{
    int i = blockIdx.x * 256 + threadIdx.x;
    if (i < n) {
        float v = w[i];
        __nv_bfloat16 h = __float2bfloat16(v);
        hi[i] = h;
        lo[i] = __float2bfloat16(v - __bfloat162float(h));
    }
}

// ---------------- mma.sync bf16 helper ----------------
__device__ __forceinline__ void mma16816(
    float& c0, float& c1, float& c2, float& c3,
    uint32_t a0, uint32_t a1, uint32_t a2, uint32_t a3,
    uint32_t b0, uint32_t b1)
{
    asm volatile(
        "mma.sync.aligned.m16n8k16.row.col.f32.bf16.bf16.f32 "
        "{%0,%1,%2,%3}, {%4,%5,%6,%7}, {%8,%9}, {%0,%1,%2,%3};"
        : "+f"(c0), "+f"(c1), "+f"(c2), "+f"(c3)
        : "r"(a0), "r"(a1), "r"(a2), "r"(a3), "r"(b0), "r"(b1));
}

// ---------------- tensor GEMM: C[m,n] = sum_k A[m,k]*W[n,k] + bias[n] ----------------
// 128x128 tile, BK=32 bf16, 8 warps (2x4), each warp 64x32 via m16n8k16.
// Split precision: C = Ah*Bh + Ah*Bl + Al*Bh (fp32 accum).
// EPI==0: scatter into q/k/v.  EPI==1: row-major C [M x N].
#define BKP 40   // smem pitch in halves (bank-conflict-free: row*20+tg distinct mod 32)
template<int EPI>
__global__ void __launch_bounds__(256, 2) mma_gemm(
    const __nv_bfloat16* __restrict__ Ah, const __nv_bfloat16* __restrict__ Al,
    const __nv_bfloat16* __restrict__ Bh, const __nv_bfloat16* __restrict__ Bl,
    const float* __restrict__ bias, float* __restrict__ C,
    float* __restrict__ Cq, float* __restrict__ Ck, float* __restrict__ Cv,
    int N, int K)
{
    __shared__ __nv_bfloat16 sAh[128*BKP], sAl[128*BKP];
    __shared__ __nv_bfloat16 sBh[128*BKP], sBl[128*BKP];

    const int tid  = threadIdx.x;
    const int lane = tid & 31;
    const int wid  = tid >> 5;
    const int wm   = (wid >> 2) * 64;      // warp m offset (0/64)
    const int wn   = (wid & 3) * 32;       // warp n offset (0/32/64/96)
    const int g    = lane >> 2;            // group row
    const int tg   = lane & 3;             // thread-in-group

    const int m0 = blockIdx.y * 128, n0 = blockIdx.x * 128;

    // staging: each thread loads 16 halves (32B) per array per iter
    const int lr = tid >> 1;               // 0..127
    const int lc = (tid & 1) * 16;         // 0 / 16
    const __nv_bfloat16* pah = Ah + (size_t)(m0 + lr) * K + lc;
    const __nv_bfloat16* pal = Al + (size_t)(m0 + lr) * K + lc;
    const __nv_bfloat16* pbh = Bh + (size_t)(n0 + lr) * K + lc;
    const __nv_bfloat16* pbl = Bl + (size_t)(n0 + lr) * K + lc;
    __nv_bfloat16* qah = &sAh[lr * BKP + lc];
    __nv_bfloat16* qal = &sAl[lr * BKP + lc];
    __nv_bfloat16* qbh = &sBh[lr * BKP + lc];
    __nv_bfloat16* qbl = &sBl[lr * BKP + lc];

    float acc[4][4][4] = {};   // [mt][nt][frag]

    for (int k0 = 0; k0 < K; k0 += 32) {
        uint4 vah0 = *(const uint4*)(pah + k0);
        uint4 vah1 = *(const uint4*)(pah + k0 + 8);
        uint4 val0 = *(const uint4*)(pal + k0);
        uint4 val1 = *(const uint4*)(pal + k0 + 8);
        uint4 vbh0 = *(const uint4*)(pbh + k0);
        uint4 vbh1 = *(const uint4*)(pbh + k0 + 8);
        uint4 vbl0 = *(const uint4*)(pbl + k0);
        uint4 vbl1 = *(const uint4*)(pbl + k0 + 8);
        __syncthreads();
        *(uint4*)(qah)     = vah0;  *(uint4*)(qah + 8) = vah1;
        *(uint4*)(qal)     = val0;  *(uint4*)(qal + 8) = val1;
        *(uint4*)(qbh)     = vbh0;  *(uint4*)(qbh + 8) = vbh1;
        *(uint4*)(qbl)     = vbl0;  *(uint4*)(qbl + 8) = vbl1;
        __syncthreads();

        #pragma unroll
        for (int ks = 0; ks < 2; ks++) {
            const int kb = ks * 16 + 2 * tg;
            uint32_t ah[4][4], bh[4][2], bl[4][2], al[4][4];
            #pragma unroll
            for (int mt = 0; mt < 4; mt++) {
                int r = wm + mt * 16 + g;
                ah[mt][0] = *(const uint32_t*)&sAh[r * BKP + kb];
                ah[mt][1] = *(const uint32_t*)&sAh[(r + 8) * BKP + kb];
                ah[mt][2] = *(const uint32_t*)&sAh[r * BKP + kb + 8];
                ah[mt][3] = *(const uint32_t*)&sAh[(r + 8) * BKP + kb + 8];
            }
            #pragma unroll
            for (int nt = 0; nt < 4; nt++) {
                int c = wn + nt * 8 + g;
                bh[nt][0] = *(const uint32_t*)&sBh[c * BKP + kb];
                bh[nt][1] = *(const uint32_t*)&sBh[c * BKP + kb + 8];
            }
            #pragma unroll
            for (int mt = 0; mt < 4; mt++)
                #pragma unroll
                for (int nt = 0; nt < 4; nt++)
                    mma16816(acc[mt][nt][0], acc[mt][nt][1], acc[mt][nt][2], acc[mt][nt][3],
                             ah[mt][0], ah[mt][1], ah[mt][2], ah[mt][3],
                             bh[nt][0], bh[nt][1]);
            #pragma unroll
            for (int nt = 0; nt < 4; nt++) {
                int c = wn + nt * 8 + g;
                bl[nt][0] = *(const uint32_t*)&sBl[c * BKP + kb];
                bl[nt][1] = *(const uint32_t*)&sBl[c * BKP + kb + 8];
            }
            #pragma unroll
            for (int mt = 0; mt < 4; mt++)
                #pragma unroll
                for (int nt = 0; nt < 4; nt++)
                    mma16816(acc[mt][nt][0], acc[mt][nt][1], acc[mt][nt][2], acc[mt][nt][3],
                             ah[mt][0], ah[mt][1], ah[mt][2], ah[mt][3],
                             bl[nt][0], bl[nt][1]);
            #pragma unroll
            for (int mt = 0; mt < 4; mt++) {
                int r = wm + mt * 16 + g;
                al[mt][0] = *(const uint32_t*)&sAl[r * BKP + kb];
                al[mt][1] = *(const uint32_t*)&sAl[(r + 8) * BKP + kb];
                al[mt][2] = *(const uint32_t*)&sAl[r * BKP + kb + 8];
                al[mt][3] = *(const uint32_t*)&sAl[(r + 8) * BKP + kb + 8];
            }
            #pragma unroll
            for (int mt = 0; mt < 4; mt++)
                #pragma unroll
                for (int nt = 0; nt < 4; nt++)
                    mma16816(acc[mt][nt][0], acc[mt][nt][1], acc[mt][nt][2], acc[mt][nt][3],
                             al[mt][0], al[mt][1], al[mt][2], al[mt][3],
                             bh[nt][0], bh[nt][1]);
        }
    }

    // epilogue: thread owns rows (g, g+8) per mt, cols (2tg, 2tg+1) per nt
    #pragma unroll
    for (int mt = 0; mt < 4; mt++) {
        #pragma unroll
        for (int half = 0; half < 2; half++) {
            int m = m0 + wm + mt * 16 + g + half * 8;
            int b_ = m >> 11;
            int s_ = m & 2047;
            #pragma unroll
            for (int nt = 0; nt < 4; nt++) {
                int n = n0 + wn + nt * 8 + 2 * tg;
                float e0 = acc[mt][nt][half*2 + 0] + __ldg(&bias[n]);
                float e1 = acc[mt][nt][half*2 + 1] + __ldg(&bias[n + 1]);
                if (EPI == 1) {
                    *(float2*)&C[(size_t)m * N + n] = make_float2(e0, e1);
                } else {
                    int h_ = n / 192;
                    int rem = n - h_ * 192;
                    int which = rem >> 6;
                    int d0 = rem & 63;
                    float* dst = (which == 0) ? Cq : (which == 1) ? Ck : Cv;
                    size_t base = ((size_t)(b_ * HH + h_) * SS + s_) * HD + d0;
                    *(float2*)&dst[base] = make_float2(e0, e1);
                }
            }
        }
    }
}

// ---------------- Flash attention v2: BM=BN=64, HD=64, 256 threads ----------------
#define ATTN_SMEM (4 * 64 * 68 * 4)
__global__ void __launch_bounds__(256, 2) attn_kernel(
    const float* __restrict__ Q, const float* __restrict__ K,
    const float* __restrict__ V, __nv_bfloat16* __restrict__ Oh,
    __nv_bfloat16* __restrict__ Ol)
{
    extern __shared__ float sm[];
    float* Qt = sm;              // [d][r]
    float* Kt = sm + 64*68;      // [d][c]
    float* Vs = sm + 2*64*68;    // [c][d]
    float* Pt = sm + 3*64*68;    // [c][r]
    int tid = threadIdx.x;
    int bh  = blockIdx.y;
    int b_  = bh / HH;
    int h_  = bh - b_ * HH;
    const float* Qg = Q + ((size_t)bh * SS + blockIdx.x * 64) * HD;
    const float* Kg = K + (size_t)bh * SS * HD;
    const float* Vg = V + (size_t)bh * SS * HD;

    int lr  = tid >> 2;
    int ld0 = (tid & 3) * 16;

    {
        float4 t0 = *(const float4*)(Qg + lr * HD + ld0);
        float4 t1 = *(const float4*)(Qg + lr * HD + ld0 + 4);
        float4 t2 = *(const float4*)(Qg + lr * HD + ld0 + 8);
        float4 t3 = *(const float4*)(Qg + lr * HD + ld0 + 12);
        Qt[(ld0+ 0)*68+lr]=t0.x; Qt[(ld0+ 1)*68+lr]=t0.y; Qt[(ld0+ 2)*68+lr]=t0.z; Qt[(ld0+ 3)*68+lr]=t0.w;
        Qt[(ld0+ 4)*68+lr]=t1.x; Qt[(ld0+ 5)*68+lr]=t1.y; Qt[(ld0+ 6)*68+lr]=t1.z; Qt[(ld0+ 7)*68+lr]=t1.w;
        Qt[(ld0+ 8)*68+lr]=t2.x; Qt[(ld0+ 9)*68+lr]=t2.y; Qt[(ld0+10)*68+lr]=t2.z; Qt[(ld0+11)*68+lr]=t2.w;
        Qt[(ld0+12)*68+lr]=t3.x; Qt[(ld0+13)*68+lr]=t3.y; Qt[(ld0+14)*68+lr]=t3.z; Qt[(ld0+15)*68+lr]=t3.w;
    }

    int ty = tid >> 4, tx = tid & 15;
    int r0 = ty * 4, c0 = tx * 4;
    float Oa[4][4] = {};
    float m_i[4], l_i[4];
    #pragma unroll
    for (int i = 0; i < 4; i++) { m_i[i] = -1e30f; l_i[i] = 0.f; }

    for (int kt = 0; kt < SS / 64; kt++) {
        __syncthreads();
        {
            const float* kr = Kg + (size_t)(kt * 64 + lr) * HD + ld0;
            float4 t0 = *(const float4*)(kr);
            float4 t1 = *(const float4*)(kr + 4);
            float4 t2 = *(const float4*)(kr + 8);
            float4 t3 = *(const float4*)(kr + 12);
            Kt[(ld0+ 0)*68+lr]=t0.x; Kt[(ld0+ 1)*68+lr]=t0.y; Kt[(ld0+ 2)*68+lr]=t0.z; Kt[(ld0+ 3)*68+lr]=t0.w;
            Kt[(ld0+ 4)*68+lr]=t1.x; Kt[(ld0+ 5)*68+lr]=t1.y; Kt[(ld0+ 6)*68+lr]=t1.z; Kt[(ld0+ 7)*68+lr]=t1.w;
            Kt[(ld0+ 8)*68+lr]=t2.x; Kt[(ld0+ 9)*68+lr]=t2.y; Kt[(ld0+10)*68+lr]=t2.z; Kt[(ld0+11)*68+lr]=t2.w;
            Kt[(ld0+12)*68+lr]=t3.x; Kt[(ld0+13)*68+lr]=t3.y; Kt[(ld0+14)*68+lr]=t3.z; Kt[(ld0+15)*68+lr]=t3.w;
            const float4* vr = (const float4*)(Vg + (size_t)(kt * 64 + lr) * HD + ld0);
            float4* vd = (float4*)&Vs[lr * 68 + ld0];
            vd[0] = vr[0]; vd[1] = vr[1]; vd[2] = vr[2]; vd[3] = vr[3];
        }
        __syncthreads();

        float s[4][4] = {};
        #pragma unroll
        for (int d = 0; d < 64; d++) {
            float4 q4 = *(const float4*)&Qt[d * 68 + r0];
            float4 k4 = *(const float4*)&Kt[d * 68 + c0];
            s[0][0]+=q4.x*k4.x; s[0][1]+=q4.x*k4.y; s[0][2]+=q4.x*k4.z; s[0][3]+=q4.x*k4.w;
            s[1][0]+=q4.y*k4.x; s[1][1]+=q4.y*k4.y; s[1][2]+=q4.y*k4.z; s[1][3]+=q4.y*k4.w;
            s[2][0]+=q4.z*k4.x; s[2][1]+=q4.z*k4.y; s[2][2]+=q4.z*k4.z; s[2][3]+=q4.z*k4.w;
            s[3][0]+=q4.w*k4.x; s[3][1]+=q4.w*k4.y; s[3][2]+=q4.w*k4.z; s[3][3]+=q4.w*k4.w;
        }

        const float sc = 0.125f;
        #pragma unroll
        for (int i = 0; i < 4; i++) {
            float rm = fmaxf(fmaxf(s[i][0], s[i][1]), fmaxf(s[i][2], s[i][3])) * sc;
            rm = fmaxf(rm, __shfl_xor_sync(0xffffffffu, rm, 1));
            rm = fmaxf(rm, __shfl_xor_sync(0xffffffffu, rm, 2));
            rm = fmaxf(rm, __shfl_xor_sync(0xffffffffu, rm, 4));
            rm = fmaxf(rm, __shfl_xor_sync(0xffffffffu, rm, 8));
            float mn = fmaxf(m_i[i], rm);
            float rs = 0.f;
            #pragma unroll
            for (int j = 0; j < 4; j++) {
                float p = __expf(s[i][j] * sc - mn);
                s[i][j] = p;
                rs += p;
            }
            rs += __shfl_xor_sync(0xffffffffu, rs, 1);
            rs += __shfl_xor_sync(0xffffffffu, rs, 2);
            rs += __shfl_xor_sync(0xffffffffu, rs, 4);
            rs += __shfl_xor_sync(0xffffffffu, rs, 8);
            float alpha = __expf(m_i[i] - mn);
            l_i[i] = l_i[i] * alpha + rs;
            m_i[i] = mn;
            #pragma unroll
            for (int j = 0; j < 4; j++) Oa[i][j] *= alpha;
        }

        #pragma unroll
        for (int i = 0; i < 4; i++)
            #pragma unroll
            for (int j = 0; j < 4; j++)
                Pt[(c0 + j) * 68 + r0 + i] = s[i][j];
        __syncthreads();

        #pragma unroll
        for (int kk = 0; kk < 64; kk++) {
            float4 p4 = *(const float4*)&Pt[kk * 68 + r0];
            float4 v4 = *(const float4*)&Vs[kk * 68 + c0];
            Oa[0][0]+=p4.x*v4.x; Oa[0][1]+=p4.x*v4.y; Oa[0][2]+=p4.x*v4.z; Oa[0][3]+=p4.x*v4.w;
            Oa[1][0]+=p4.y*v4.x; Oa[1][1]+=p4.y*v4.y; Oa[1][2]+=p4.y*v4.z; Oa[1][3]+=p4.y*v4.w;
            Oa[2][0]+=p4.z*v4.x; Oa[2][1]+=p4.z*v4.y; Oa[2][2]+=p4.z*v4.z; Oa[2][3]+=p4.z*v4.w;
            Oa[3][0]+=p4.w*v4.x; Oa[3][1]+=p4.w*v4.y; Oa[3][2]+=p4.w*v4.z; Oa[3][3]+=p4.w*v4.w;
        }
    }

    int s_base = blockIdx.x * 64 + r0;
    #pragma unroll
    for (int i = 0; i < 4; i++) {
        float inv = 1.0f / l_i[i];
        size_t base = ((size_t)(b_ * SS + s_base + i)) * EE + h_ * HD + c0;
        #pragma unroll
        for (int j = 0; j < 4; j++) {
            float val = Oa[i][j] * inv;
            __nv_bfloat16 h = __float2bfloat16(val);
            Oh[base + j] = h;
            Ol[base + j] = __float2bfloat16(val - __bfloat162float(h));
        }
    }
}

// ---------------- launch ----------------
extern "C" void kernel_launch(void* const* d_in, const int* in_sizes, int n_in,
                              void* d_out, int out_size)
{
    const float* x     = (const float*)d_in[0];
    const float* gamma = (const float*)d_in[1];
    const float* beta  = (const float*)d_in[2];
    const float* Wqkv  = (const float*)d_in[3];
    const float* bqkv  = (const float*)d_in[4];
    const float* Wo    = (const float*)d_in[5];
    const float* bo    = (const float*)d_in[6];
    float* out = (float*)d_out;

    __nv_bfloat16 *xh, *xl, *wqh, *wql, *woh, *wol, *oh, *ol;
    float *q, *k, *v;
    cudaGetSymbolAddress((void**)&xh,  g_xh);
    cudaGetSymbolAddress((void**)&xl,  g_xl);
    cudaGetSymbolAddress((void**)&wqh, g_wqh);
    cudaGetSymbolAddress((void**)&wql, g_wql);
    cudaGetSymbolAddress((void**)&woh, g_woh);
    cudaGetSymbolAddress((void**)&wol, g_wol);
    cudaGetSymbolAddress((void**)&q,   g_q);
    cudaGetSymbolAddress((void**)&k,   g_k);
    cudaGetSymbolAddress((void**)&v,   g_v);
    cudaGetSymbolAddress((void**)&oh,  g_oh);
    cudaGetSymbolAddress((void**)&ol,  g_ol);

    cudaFuncSetAttribute(attn_kernel, cudaFuncAttributeMaxDynamicSharedMemorySize, ATTN_SMEM);

    ln_kernel<<<MROWS, 256>>>(x, gamma, beta, xh, xl);
    cvt_kernel<<<(NQKV*EE + 255)/256, 256>>>(Wqkv, wqh, wql, NQKV*EE);
    cvt_kernel<<<(EE*EE   + 255)/256, 256>>>(Wo,   woh, wol, EE*EE);

    mma_gemm<0><<<dim3(NQKV/128, MROWS/128), 256>>>(
        xh, xl, wqh, wql, bqkv, nullptr, q, k, v, NQKV, EE);

    attn_kernel<<<dim3(SS/64, BB*HH), 256, ATTN_SMEM>>>(q, k, v, oh, ol);

    mma_gemm<1><<<dim3(EE/128, MROWS/128), 256>>>(
        oh, ol, woh, wol, bo, out, nullptr, nullptr, nullptr, EE, EE);
}

// round 5
// speedup vs baseline: 9.2906x; 1.8585x over previous
#include <cuda_runtime.h>
#include <cuda_bf16.h>
#include <math.h>
#include <cstdint>

#define BB 2
#define SS 2048
#define EE 768
#define HH 12
#define HD 64
#define MROWS (BB*SS)          // 4096
#define NQKV (3*EE)            // 2304
#define LN_EPS 1e-5f

// ---------------- scratch (no allocations allowed) ----------------
__device__ __align__(16) __nv_bfloat16 g_xh[MROWS*EE];
__device__ __align__(16) __nv_bfloat16 g_xl[MROWS*EE];
__device__ __align__(16) __nv_bfloat16 g_wqh[NQKV*EE];
__device__ __align__(16) __nv_bfloat16 g_wql[NQKV*EE];
__device__ __align__(16) __nv_bfloat16 g_woh[EE*EE];
__device__ __align__(16) __nv_bfloat16 g_wol[EE*EE];
__device__ __align__(16) __nv_bfloat16 g_qh[BB*HH*SS*HD];   // [b,h,s,d] planes
__device__ __align__(16) __nv_bfloat16 g_ql[BB*HH*SS*HD];
__device__ __align__(16) __nv_bfloat16 g_kh[BB*HH*SS*HD];
__device__ __align__(16) __nv_bfloat16 g_kl[BB*HH*SS*HD];
__device__ __align__(16) __nv_bfloat16 g_vh[BB*HH*SS*HD];
__device__ __align__(16) __nv_bfloat16 g_vl[BB*HH*SS*HD];
__device__ __align__(16) __nv_bfloat16 g_oh[MROWS*EE];
__device__ __align__(16) __nv_bfloat16 g_ol[MROWS*EE];

// ---------------- LayerNorm ----------------
__global__ void __launch_bounds__(256) ln_kernel(
    const float* __restrict__ x, const float* __restrict__ gamma,
    const float* __restrict__ beta, __nv_bfloat16* __restrict__ xh,
    __nv_bfloat16* __restrict__ xl)
{
    int row = blockIdx.x;
    int tid = threadIdx.x;
    const float* xr = x + (size_t)row * EE;
    float v0 = xr[tid], v1 = xr[tid+256], v2 = xr[tid+512];
    float s  = v0 + v1 + v2;
    float s2 = v0*v0 + v1*v1 + v2*v2;
    #pragma unroll
    for (int o = 16; o; o >>= 1) {
        s  += __shfl_xor_sync(0xffffffffu, s,  o);
        s2 += __shfl_xor_sync(0xffffffffu, s2, o);
    }
    __shared__ float sh0[8], sh1[8];
    int w = tid >> 5, l = tid & 31;
    if (l == 0) { sh0[w] = s; sh1[w] = s2; }
    __syncthreads();
    if (tid < 32) {
        s  = (l < 8) ? sh0[l] : 0.f;
        s2 = (l < 8) ? sh1[l] : 0.f;
        #pragma unroll
        for (int o = 4; o; o >>= 1) {
            s  += __shfl_xor_sync(0xffffffffu, s,  o);
            s2 += __shfl_xor_sync(0xffffffffu, s2, o);
        }
        if (l == 0) { sh0[0] = s; sh1[0] = s2; }
    }
    __syncthreads();
    s = sh0[0]; s2 = sh1[0];
    float mu   = s * (1.0f / EE);
    float var  = s2 * (1.0f / EE) - mu * mu;
    float rstd = rsqrtf(var + LN_EPS);
    size_t base = (size_t)row * EE;
    #pragma unroll
    for (int p = 0; p < 3; p++) {
        int c = tid + p * 256;
        float v = (p == 0) ? v0 : (p == 1) ? v1 : v2;
        float y = (v - mu) * rstd * gamma[c] + beta[c];
        __nv_bfloat16 h = __float2bfloat16(y);
        xh[base + c] = h;
        xl[base + c] = __float2bfloat16(y - __bfloat162float(h));
    }
}

// ---------------- fp32 -> bf16 hi/lo split ----------------
__global__ void __launch_bounds__(256) cvt_kernel(
    const float* __restrict__ w, __nv_bfloat16* __restrict__ hi,
    __nv_bfloat16* __restrict__ lo, int n)
{
    int i = blockIdx.x * 256 + threadIdx.x;
    if (i < n) {
        float v = w[i];
        __nv_bfloat16 h = __float2bfloat16(v);
        hi[i] = h;
        lo[i] = __float2bfloat16(v - __bfloat162float(h));
    }
}

// ---------------- mma.sync bf16 helper ----------------
__device__ __forceinline__ void mma16816(
    float& c0, float& c1, float& c2, float& c3,
    uint32_t a0, uint32_t a1, uint32_t a2, uint32_t a3,
    uint32_t b0, uint32_t b1)
{
    asm volatile(
        "mma.sync.aligned.m16n8k16.row.col.f32.bf16.bf16.f32 "
        "{%0,%1,%2,%3}, {%4,%5,%6,%7}, {%8,%9}, {%0,%1,%2,%3};"
        : "+f"(c0), "+f"(c1), "+f"(c2), "+f"(c3)
        : "r"(a0), "r"(a1), "r"(a2), "r"(a3), "r"(b0), "r"(b1));
}

__device__ __forceinline__ __nv_bfloat162 pack_bf162(float a, float b) {
    float2 t; t.x = a; t.y = b;
    return __float22bfloat162_rn(t);
}

// ---------------- tensor GEMM: C[m,n] = sum_k A[m,k]*W[n,k] + bias[n] ----------------
#define BKP 40
template<int EPI>
__global__ void __launch_bounds__(256, 2) mma_gemm(
    const __nv_bfloat16* __restrict__ Ah, const __nv_bfloat16* __restrict__ Al,
    const __nv_bfloat16* __restrict__ Bh, const __nv_bfloat16* __restrict__ Bl,
    const float* __restrict__ bias, float* __restrict__ C,
    __nv_bfloat16* __restrict__ Pqh, __nv_bfloat16* __restrict__ Pql,
    __nv_bfloat16* __restrict__ Pkh, __nv_bfloat16* __restrict__ Pkl,
    __nv_bfloat16* __restrict__ Pvh, __nv_bfloat16* __restrict__ Pvl,
    int N, int K)
{
    __shared__ __nv_bfloat16 sAh[128*BKP], sAl[128*BKP];
    __shared__ __nv_bfloat16 sBh[128*BKP], sBl[128*BKP];

    const int tid  = threadIdx.x;
    const int lane = tid & 31;
    const int wid  = tid >> 5;
    const int wm   = (wid >> 2) * 64;
    const int wn   = (wid & 3) * 32;
    const int g    = lane >> 2;
    const int tg   = lane & 3;

    const int m0 = blockIdx.y * 128, n0 = blockIdx.x * 128;

    const int lr = tid >> 1;
    const int lc = (tid & 1) * 16;
    const __nv_bfloat16* pah = Ah + (size_t)(m0 + lr) * K + lc;
    const __nv_bfloat16* pal = Al + (size_t)(m0 + lr) * K + lc;
    const __nv_bfloat16* pbh = Bh + (size_t)(n0 + lr) * K + lc;
    const __nv_bfloat16* pbl = Bl + (size_t)(n0 + lr) * K + lc;
    __nv_bfloat16* qah = &sAh[lr * BKP + lc];
    __nv_bfloat16* qal = &sAl[lr * BKP + lc];
    __nv_bfloat16* qbh = &sBh[lr * BKP + lc];
    __nv_bfloat16* qbl = &sBl[lr * BKP + lc];

    float acc[4][4][4] = {};

    for (int k0 = 0; k0 < K; k0 += 32) {
        uint4 vah0 = *(const uint4*)(pah + k0);
        uint4 vah1 = *(const uint4*)(pah + k0 + 8);
        uint4 val0 = *(const uint4*)(pal + k0);
        uint4 val1 = *(const uint4*)(pal + k0 + 8);
        uint4 vbh0 = *(const uint4*)(pbh + k0);
        uint4 vbh1 = *(const uint4*)(pbh + k0 + 8);
        uint4 vbl0 = *(const uint4*)(pbl + k0);
        uint4 vbl1 = *(const uint4*)(pbl + k0 + 8);
        __syncthreads();
        *(uint4*)(qah)     = vah0;  *(uint4*)(qah + 8) = vah1;
        *(uint4*)(qal)     = val0;  *(uint4*)(qal + 8) = val1;
        *(uint4*)(qbh)     = vbh0;  *(uint4*)(qbh + 8) = vbh1;
        *(uint4*)(qbl)     = vbl0;  *(uint4*)(qbl + 8) = vbl1;
        __syncthreads();

        #pragma unroll
        for (int ks = 0; ks < 2; ks++) {
            const int kb = ks * 16 + 2 * tg;
            uint32_t ah[4][4], bh[4][2], bl[4][2], al[4][4];
            #pragma unroll
            for (int mt = 0; mt < 4; mt++) {
                int r = wm + mt * 16 + g;
                ah[mt][0] = *(const uint32_t*)&sAh[r * BKP + kb];
                ah[mt][1] = *(const uint32_t*)&sAh[(r + 8) * BKP + kb];
                ah[mt][2] = *(const uint32_t*)&sAh[r * BKP + kb + 8];
                ah[mt][3] = *(const uint32_t*)&sAh[(r + 8) * BKP + kb + 8];
            }
            #pragma unroll
            for (int nt = 0; nt < 4; nt++) {
                int c = wn + nt * 8 + g;
                bh[nt][0] = *(const uint32_t*)&sBh[c * BKP + kb];
                bh[nt][1] = *(const uint32_t*)&sBh[c * BKP + kb + 8];
            }
            #pragma unroll
            for (int mt = 0; mt < 4; mt++)
                #pragma unroll
                for (int nt = 0; nt < 4; nt++)
                    mma16816(acc[mt][nt][0], acc[mt][nt][1], acc[mt][nt][2], acc[mt][nt][3],
                             ah[mt][0], ah[mt][1], ah[mt][2], ah[mt][3],
                             bh[nt][0], bh[nt][1]);
            #pragma unroll
            for (int nt = 0; nt < 4; nt++) {
                int c = wn + nt * 8 + g;
                bl[nt][0] = *(const uint32_t*)&sBl[c * BKP + kb];
                bl[nt][1] = *(const uint32_t*)&sBl[c * BKP + kb + 8];
            }
            #pragma unroll
            for (int mt = 0; mt < 4; mt++)
                #pragma unroll
                for (int nt = 0; nt < 4; nt++)
                    mma16816(acc[mt][nt][0], acc[mt][nt][1], acc[mt][nt][2], acc[mt][nt][3],
                             ah[mt][0], ah[mt][1], ah[mt][2], ah[mt][3],
                             bl[nt][0], bl[nt][1]);
            #pragma unroll
            for (int mt = 0; mt < 4; mt++) {
                int r = wm + mt * 16 + g;
                al[mt][0] = *(const uint32_t*)&sAl[r * BKP + kb];
                al[mt][1] = *(const uint32_t*)&sAl[(r + 8) * BKP + kb];
                al[mt][2] = *(const uint32_t*)&sAl[r * BKP + kb + 8];
                al[mt][3] = *(const uint32_t*)&sAl[(r + 8) * BKP + kb + 8];
            }
            #pragma unroll
            for (int mt = 0; mt < 4; mt++)
                #pragma unroll
                for (int nt = 0; nt < 4; nt++)
                    mma16816(acc[mt][nt][0], acc[mt][nt][1], acc[mt][nt][2], acc[mt][nt][3],
                             al[mt][0], al[mt][1], al[mt][2], al[mt][3],
                             bh[nt][0], bh[nt][1]);
        }
    }

    #pragma unroll
    for (int mt = 0; mt < 4; mt++) {
        #pragma unroll
        for (int half = 0; half < 2; half++) {
            int m = m0 + wm + mt * 16 + g + half * 8;
            int b_ = m >> 11;
            int s_ = m & 2047;
            #pragma unroll
            for (int nt = 0; nt < 4; nt++) {
                int n = n0 + wn + nt * 8 + 2 * tg;
                float e0 = acc[mt][nt][half*2 + 0] + __ldg(&bias[n]);
                float e1 = acc[mt][nt][half*2 + 1] + __ldg(&bias[n + 1]);
                if (EPI == 1) {
                    *(float2*)&C[(size_t)m * N + n] = make_float2(e0, e1);
                } else {
                    int h_ = n / 192;
                    int rem = n - h_ * 192;
                    int which = rem >> 6;
                    int d0 = rem & 63;
                    __nv_bfloat16* dh = (which == 0) ? Pqh : (which == 1) ? Pkh : Pvh;
                    __nv_bfloat16* dl = (which == 0) ? Pql : (which == 1) ? Pkl : Pvl;
                    size_t base = ((size_t)(b_ * HH + h_) * SS + s_) * HD + d0;
                    __nv_bfloat162 h2 = pack_bf162(e0, e1);
                    __nv_bfloat162 l2 = pack_bf162(e0 - __low2float(h2), e1 - __high2float(h2));
                    *(__nv_bfloat162*)&dh[base] = h2;
                    *(__nv_bfloat162*)&dl[base] = l2;
                }
            }
        }
    }
}

// ---------------- Flash attention on tensor cores ----------------
// BM=128, BN=64, HD=64. 8 warps x 16 rows. Split-precision 3-pass for QK^T and PV.
#define AP 72
#define ATT_SMEM ((128*AP*2 + 64*AP*4) * 2)
__global__ void __launch_bounds__(256) attn_mma(
    const __nv_bfloat16* __restrict__ qh, const __nv_bfloat16* __restrict__ ql,
    const __nv_bfloat16* __restrict__ kh, const __nv_bfloat16* __restrict__ kl,
    const __nv_bfloat16* __restrict__ vh, const __nv_bfloat16* __restrict__ vl,
    __nv_bfloat16* __restrict__ Oh, __nv_bfloat16* __restrict__ Ol)
{
    extern __shared__ __nv_bfloat16 smb[];
    __nv_bfloat16* sQh = smb;
    __nv_bfloat16* sQl = smb + 128*AP;
    __nv_bfloat16* sKh = smb + 256*AP;
    __nv_bfloat16* sKl = smb + 320*AP;
    __nv_bfloat16* sVh = smb + 384*AP;   // transposed [d][kv]
    __nv_bfloat16* sVl = smb + 448*AP;

    const int tid  = threadIdx.x;
    const int lane = tid & 31;
    const int wid  = tid >> 5;
    const int g    = lane >> 2;
    const int tg   = lane & 3;
    const int wm   = wid * 16;

    const int bh = blockIdx.y;
    const int b_ = bh / HH;
    const int h_ = bh - b_ * HH;
    const size_t headoff = (size_t)bh * SS * HD;

    {   // Q staging (once): threads 0-127 hi rows, 128-255 lo rows
        int row = tid & 127;
        const __nv_bfloat16* src = ((tid < 128) ? qh : ql) + headoff
                                 + (size_t)(blockIdx.x * 128 + row) * HD;
        __nv_bfloat16* dst = ((tid < 128) ? sQh : sQl) + row * AP;
        #pragma unroll
        for (int c = 0; c < 8; c++)
            *(uint4*)&dst[c * 8] = ((const uint4*)src)[c];
    }

    float oacc[8][4] = {};
    float m0_ = -1e30f, m1_ = -1e30f, l0_ = 0.f, l1_ = 0.f;
    const float sc = 0.125f;   // 1/sqrt(64)

    for (int kt = 0; kt < SS / 64; kt++) {
        __syncthreads();
        {   // K/V staging: sel 0=Kh,1=Kl,2=Vh(T),3=Vl(T); row = kv index
            int sel = tid >> 6;
            int row = tid & 63;
            size_t off = headoff + (size_t)(kt * 64 + row) * HD;
            if (sel < 2) {
                const __nv_bfloat16* src = (sel == 0 ? kh : kl) + off;
                __nv_bfloat16* dst = (sel == 0 ? sKh : sKl) + row * AP;
                #pragma unroll
                for (int c = 0; c < 8; c++)
                    *(uint4*)&dst[c * 8] = ((const uint4*)src)[c];
            } else {
                const __nv_bfloat16* src = (sel == 2 ? vh : vl) + off;
                __nv_bfloat16* dst = (sel == 2 ? sVh : sVl) + row;   // column kv=row
                #pragma unroll
                for (int c = 0; c < 8; c++) {
                    uint4 t = ((const uint4*)src)[c];
                    const __nv_bfloat16* tp = (const __nv_bfloat16*)&t;
                    #pragma unroll
                    for (int u = 0; u < 8; u++)
                        dst[(c * 8 + u) * AP] = tp[u];
                }
            }
        }
        __syncthreads();

        // ---- S = Q K^T (3-pass) ----
        float sacc[8][4] = {};
        #pragma unroll
        for (int kc = 0; kc < 4; kc++) {
            const int kb = kc * 16 + 2 * tg;
            uint32_t aqh[4], aql[4], bk[8][2];
            {
                int r = wm + g;
                aqh[0] = *(const uint32_t*)&sQh[r * AP + kb];
                aqh[1] = *(const uint32_t*)&sQh[(r + 8) * AP + kb];
                aqh[2] = *(const uint32_t*)&sQh[r * AP + kb + 8];
                aqh[3] = *(const uint32_t*)&sQh[(r + 8) * AP + kb + 8];
                aql[0] = *(const uint32_t*)&sQl[r * AP + kb];
                aql[1] = *(const uint32_t*)&sQl[(r + 8) * AP + kb];
                aql[2] = *(const uint32_t*)&sQl[r * AP + kb + 8];
                aql[3] = *(const uint32_t*)&sQl[(r + 8) * AP + kb + 8];
            }
            #pragma unroll
            for (int nt = 0; nt < 8; nt++) {
                int c = nt * 8 + g;
                bk[nt][0] = *(const uint32_t*)&sKh[c * AP + kb];
                bk[nt][1] = *(const uint32_t*)&sKh[c * AP + kb + 8];
            }
            #pragma unroll
            for (int nt = 0; nt < 8; nt++)
                mma16816(sacc[nt][0], sacc[nt][1], sacc[nt][2], sacc[nt][3],
                         aqh[0], aqh[1], aqh[2], aqh[3], bk[nt][0], bk[nt][1]);
            #pragma unroll
            for (int nt = 0; nt < 8; nt++)
                mma16816(sacc[nt][0], sacc[nt][1], sacc[nt][2], sacc[nt][3],
                         aql[0], aql[1], aql[2], aql[3], bk[nt][0], bk[nt][1]);
            #pragma unroll
            for (int nt = 0; nt < 8; nt++) {
                int c = nt * 8 + g;
                bk[nt][0] = *(const uint32_t*)&sKl[c * AP + kb];
                bk[nt][1] = *(const uint32_t*)&sKl[c * AP + kb + 8];
            }
            #pragma unroll
            for (int nt = 0; nt < 8; nt++)
                mma16816(sacc[nt][0], sacc[nt][1], sacc[nt][2], sacc[nt][3],
                         aqh[0], aqh[1], aqh[2], aqh[3], bk[nt][0], bk[nt][1]);
        }

        // ---- online softmax (rows g and g+8 of warp tile) ----
        float rm0 = -1e30f, rm1 = -1e30f;
        #pragma unroll
        for (int nt = 0; nt < 8; nt++) {
            rm0 = fmaxf(rm0, fmaxf(sacc[nt][0], sacc[nt][1]));
            rm1 = fmaxf(rm1, fmaxf(sacc[nt][2], sacc[nt][3]));
        }
        rm0 *= sc; rm1 *= sc;
        rm0 = fmaxf(rm0, __shfl_xor_sync(0xffffffffu, rm0, 1));
        rm0 = fmaxf(rm0, __shfl_xor_sync(0xffffffffu, rm0, 2));
        rm1 = fmaxf(rm1, __shfl_xor_sync(0xffffffffu, rm1, 1));
        rm1 = fmaxf(rm1, __shfl_xor_sync(0xffffffffu, rm1, 2));
        float mn0 = fmaxf(m0_, rm0), mn1 = fmaxf(m1_, rm1);
        float rs0 = 0.f, rs1 = 0.f;
        #pragma unroll
        for (int nt = 0; nt < 8; nt++) {
            sacc[nt][0] = __expf(sacc[nt][0] * sc - mn0);
            sacc[nt][1] = __expf(sacc[nt][1] * sc - mn0);
            sacc[nt][2] = __expf(sacc[nt][2] * sc - mn1);
            sacc[nt][3] = __expf(sacc[nt][3] * sc - mn1);
            rs0 += sacc[nt][0] + sacc[nt][1];
            rs1 += sacc[nt][2] + sacc[nt][3];
        }
        rs0 += __shfl_xor_sync(0xffffffffu, rs0, 1);
        rs0 += __shfl_xor_sync(0xffffffffu, rs0, 2);
        rs1 += __shfl_xor_sync(0xffffffffu, rs1, 1);
        rs1 += __shfl_xor_sync(0xffffffffu, rs1, 2);
        float al0 = __expf(m0_ - mn0), al1 = __expf(m1_ - mn1);
        l0_ = l0_ * al0 + rs0;  m0_ = mn0;
        l1_ = l1_ * al1 + rs1;  m1_ = mn1;
        #pragma unroll
        for (int nt = 0; nt < 8; nt++) {
            oacc[nt][0] *= al0; oacc[nt][1] *= al0;
            oacc[nt][2] *= al1; oacc[nt][3] *= al1;
        }

        // ---- pack P fragments in registers (hi + lo) ----
        uint32_t ph[4][4], pl[4][4];
        #pragma unroll
        for (int kc = 0; kc < 4; kc++) {
            #pragma unroll
            for (int e = 0; e < 2; e++) {        // e=0: rows g / e=1: rows g+8 pair index
                // a0/a1 (k 0..7): from nt=2kc ; a2/a3 (k 8..15): from nt=2kc+1
            }
            __nv_bfloat162 h0 = pack_bf162(sacc[2*kc][0],   sacc[2*kc][1]);
            __nv_bfloat162 h1 = pack_bf162(sacc[2*kc][2],   sacc[2*kc][3]);
            __nv_bfloat162 h2 = pack_bf162(sacc[2*kc+1][0], sacc[2*kc+1][1]);
            __nv_bfloat162 h3 = pack_bf162(sacc[2*kc+1][2], sacc[2*kc+1][3]);
            ph[kc][0] = *(uint32_t*)&h0; ph[kc][1] = *(uint32_t*)&h1;
            ph[kc][2] = *(uint32_t*)&h2; ph[kc][3] = *(uint32_t*)&h3;
            __nv_bfloat162 l0 = pack_bf162(sacc[2*kc][0]   - __low2float(h0), sacc[2*kc][1]   - __high2float(h0));
            __nv_bfloat162 l1 = pack_bf162(sacc[2*kc][2]   - __low2float(h1), sacc[2*kc][3]   - __high2float(h1));
            __nv_bfloat162 l2 = pack_bf162(sacc[2*kc+1][0] - __low2float(h2), sacc[2*kc+1][1] - __high2float(h2));
            __nv_bfloat162 l3 = pack_bf162(sacc[2*kc+1][2] - __low2float(h3), sacc[2*kc+1][3] - __high2float(h3));
            pl[kc][0] = *(uint32_t*)&l0; pl[kc][1] = *(uint32_t*)&l1;
            pl[kc][2] = *(uint32_t*)&l2; pl[kc][3] = *(uint32_t*)&l3;
        }

        // ---- O += P V (3-pass) ----
        #pragma unroll
        for (int kc = 0; kc < 4; kc++) {
            const int kb = kc * 16 + 2 * tg;
            uint32_t bv[8][2];
            #pragma unroll
            for (int nt = 0; nt < 8; nt++) {
                int c = nt * 8 + g;
                bv[nt][0] = *(const uint32_t*)&sVh[c * AP + kb];
                bv[nt][1] = *(const uint32_t*)&sVh[c * AP + kb + 8];
            }
            #pragma unroll
            for (int nt = 0; nt < 8; nt++)
                mma16816(oacc[nt][0], oacc[nt][1], oacc[nt][2], oacc[nt][3],
                         ph[kc][0], ph[kc][1], ph[kc][2], ph[kc][3], bv[nt][0], bv[nt][1]);
            #pragma unroll
            for (int nt = 0; nt < 8; nt++)
                mma16816(oacc[nt][0], oacc[nt][1], oacc[nt][2], oacc[nt][3],
                         pl[kc][0], pl[kc][1], pl[kc][2], pl[kc][3], bv[nt][0], bv[nt][1]);
            #pragma unroll
            for (int nt = 0; nt < 8; nt++) {
                int c = nt * 8 + g;
                bv[nt][0] = *(const uint32_t*)&sVl[c * AP + kb];
                bv[nt][1] = *(const uint32_t*)&sVl[c * AP + kb + 8];
            }
            #pragma unroll
            for (int nt = 0; nt < 8; nt++)
                mma16816(oacc[nt][0], oacc[nt][1], oacc[nt][2], oacc[nt][3],
                         ph[kc][0], ph[kc][1], ph[kc][2], ph[kc][3], bv[nt][0], bv[nt][1]);
        }
    }

    // ---- epilogue: normalize and emit bf16 hi/lo planes ----
    float inv0 = 1.0f / l0_, inv1 = 1.0f / l1_;
    int sbase = blockIdx.x * 128 + wm;
    size_t ob0 = ((size_t)(b_ * SS + sbase + g))     * EE + h_ * HD + 2 * tg;
    size_t ob1 = ((size_t)(b_ * SS + sbase + g + 8)) * EE + h_ * HD + 2 * tg;
    #pragma unroll
    for (int nt = 0; nt < 8; nt++) {
        int d = nt * 8;
        float e0 = oacc[nt][0] * inv0, e1 = oacc[nt][1] * inv0;
        __nv_bfloat162 h2 = pack_bf162(e0, e1);
        __nv_bfloat162 l2 = pack_bf162(e0 - __low2float(h2), e1 - __high2float(h2));
        *(__nv_bfloat162*)&Oh[ob0 + d] = h2;
        *(__nv_bfloat162*)&Ol[ob0 + d] = l2;
        e0 = oacc[nt][2] * inv1; e1 = oacc[nt][3] * inv1;
        h2 = pack_bf162(e0, e1);
        l2 = pack_bf162(e0 - __low2float(h2), e1 - __high2float(h2));
        *(__nv_bfloat162*)&Oh[ob1 + d] = h2;
        *(__nv_bfloat162*)&Ol[ob1 + d] = l2;
    }
}

// ---------------- launch ----------------
extern "C" void kernel_launch(void* const* d_in, const int* in_sizes, int n_in,
                              void* d_out, int out_size)
{
    const float* x     = (const float*)d_in[0];
    const float* gamma = (const float*)d_in[1];
    const float* beta  = (const float*)d_in[2];
    const float* Wqkv  = (const float*)d_in[3];
    const float* bqkv  = (const float*)d_in[4];
    const float* Wo    = (const float*)d_in[5];
    const float* bo    = (const float*)d_in[6];
    float* out = (float*)d_out;

    __nv_bfloat16 *xh, *xl, *wqh, *wql, *woh, *wol, *oh, *ol;
    __nv_bfloat16 *qh, *ql, *kh, *kl, *vh, *vl;
    cudaGetSymbolAddress((void**)&xh,  g_xh);
    cudaGetSymbolAddress((void**)&xl,  g_xl);
    cudaGetSymbolAddress((void**)&wqh, g_wqh);
    cudaGetSymbolAddress((void**)&wql, g_wql);
    cudaGetSymbolAddress((void**)&woh, g_woh);
    cudaGetSymbolAddress((void**)&wol, g_wol);
    cudaGetSymbolAddress((void**)&qh,  g_qh);
    cudaGetSymbolAddress((void**)&ql,  g_ql);
    cudaGetSymbolAddress((void**)&kh,  g_kh);
    cudaGetSymbolAddress((void**)&kl,  g_kl);
    cudaGetSymbolAddress((void**)&vh,  g_vh);
    cudaGetSymbolAddress((void**)&vl,  g_vl);
    cudaGetSymbolAddress((void**)&oh,  g_oh);
    cudaGetSymbolAddress((void**)&ol,  g_ol);

    cudaFuncSetAttribute(attn_mma, cudaFuncAttributeMaxDynamicSharedMemorySize, ATT_SMEM);

    ln_kernel<<<MROWS, 256>>>(x, gamma, beta, xh, xl);
    cvt_kernel<<<(NQKV*EE + 255)/256, 256>>>(Wqkv, wqh, wql, NQKV*EE);
    cvt_kernel<<<(EE*EE   + 255)/256, 256>>>(Wo,   woh, wol, EE*EE);

    mma_gemm<0><<<dim3(NQKV/128, MROWS/128), 256>>>(
        xh, xl, wqh, wql, bqkv, nullptr, qh, ql, kh, kl, vh, vl, NQKV, EE);

    attn_mma<<<dim3(SS/128, BB*HH), 256, ATT_SMEM>>>(qh, ql, kh, kl, vh, vl, oh, ol);

    mma_gemm<1><<<dim3(EE/128, MROWS/128), 256>>>(
        oh, ol, woh, wol, bo, out, nullptr, nullptr, nullptr, nullptr, nullptr, nullptr, EE, EE);
}

// round 6
// speedup vs baseline: 10.7885x; 1.1612x over previous
#include <cuda_runtime.h>
#include <cuda_bf16.h>
#include <math.h>
#include <cstdint>

#define BB 2
#define SS 2048
#define EE 768
#define HH 12
#define HD 64
#define MROWS (BB*SS)          // 4096
#define NQKV (3*EE)            // 2304
#define LN_EPS 1e-5f

// ---------------- scratch (no allocations allowed) ----------------
__device__ __align__(16) __nv_bfloat16 g_xh[MROWS*EE];
__device__ __align__(16) __nv_bfloat16 g_xl[MROWS*EE];
__device__ __align__(16) __nv_bfloat16 g_wqh[NQKV*EE];
__device__ __align__(16) __nv_bfloat16 g_wql[NQKV*EE];
__device__ __align__(16) __nv_bfloat16 g_woh[EE*EE];
__device__ __align__(16) __nv_bfloat16 g_wol[EE*EE];
__device__ __align__(16) __nv_bfloat16 g_qh[BB*HH*SS*HD];
__device__ __align__(16) __nv_bfloat16 g_ql[BB*HH*SS*HD];
__device__ __align__(16) __nv_bfloat16 g_kh[BB*HH*SS*HD];
__device__ __align__(16) __nv_bfloat16 g_kl[BB*HH*SS*HD];
__device__ __align__(16) __nv_bfloat16 g_vh[BB*HH*SS*HD];
__device__ __align__(16) __nv_bfloat16 g_vl[BB*HH*SS*HD];
__device__ __align__(16) __nv_bfloat16 g_oh[MROWS*EE];
__device__ __align__(16) __nv_bfloat16 g_ol[MROWS*EE];

// ================= helpers =================
__device__ __forceinline__ uint32_t smem_u32(const void* p) {
    uint32_t a;
    asm("{ .reg .u64 t; cvta.to.shared.u64 t, %1; cvt.u32.u64 %0, t; }" : "=r"(a) : "l"(p));
    return a;
}
__device__ __forceinline__ void cp16(uint32_t dst, const void* src) {
    asm volatile("cp.async.cg.shared.global [%0], [%1], 16;" :: "r"(dst), "l"(src));
}
#define CP_COMMIT() asm volatile("cp.async.commit_group;" ::: "memory")
#define CP_WAIT0()  asm volatile("cp.async.wait_group 0;" ::: "memory")

__device__ __forceinline__ void ldmx4(uint32_t* r, uint32_t a) {
    asm volatile("ldmatrix.sync.aligned.m8n8.x4.shared.b16 {%0,%1,%2,%3}, [%4];"
        : "=r"(r[0]), "=r"(r[1]), "=r"(r[2]), "=r"(r[3]) : "r"(a));
}
__device__ __forceinline__ void ldmx4t(uint32_t* r, uint32_t a) {
    asm volatile("ldmatrix.sync.aligned.m8n8.x4.trans.shared.b16 {%0,%1,%2,%3}, [%4];"
        : "=r"(r[0]), "=r"(r[1]), "=r"(r[2]), "=r"(r[3]) : "r"(a));
}
__device__ __forceinline__ void mma16816(
    float& c0, float& c1, float& c2, float& c3,
    uint32_t a0, uint32_t a1, uint32_t a2, uint32_t a3,
    uint32_t b0, uint32_t b1)
{
    asm volatile(
        "mma.sync.aligned.m16n8k16.row.col.f32.bf16.bf16.f32 "
        "{%0,%1,%2,%3}, {%4,%5,%6,%7}, {%8,%9}, {%0,%1,%2,%3};"
        : "+f"(c0), "+f"(c1), "+f"(c2), "+f"(c3)
        : "r"(a0), "r"(a1), "r"(a2), "r"(a3), "r"(b0), "r"(b1));
}
__device__ __forceinline__ __nv_bfloat162 pack_bf162(float a, float b) {
    float2 t; t.x = a; t.y = b;
    return __float22bfloat162_rn(t);
}

// ---------------- LayerNorm ----------------
__global__ void __launch_bounds__(256) ln_kernel(
    const float* __restrict__ x, const float* __restrict__ gamma,
    const float* __restrict__ beta, __nv_bfloat16* __restrict__ xh,
    __nv_bfloat16* __restrict__ xl)
{
    int row = blockIdx.x;
    int tid = threadIdx.x;
    const float* xr = x + (size_t)row * EE;
    float v0 = xr[tid], v1 = xr[tid+256], v2 = xr[tid+512];
    float s  = v0 + v1 + v2;
    float s2 = v0*v0 + v1*v1 + v2*v2;
    #pragma unroll
    for (int o = 16; o; o >>= 1) {
        s  += __shfl_xor_sync(0xffffffffu, s,  o);
        s2 += __shfl_xor_sync(0xffffffffu, s2, o);
    }
    __shared__ float sh0[8], sh1[8];
    int w = tid >> 5, l = tid & 31;
    if (l == 0) { sh0[w] = s; sh1[w] = s2; }
    __syncthreads();
    if (tid < 32) {
        s  = (l < 8) ? sh0[l] : 0.f;
        s2 = (l < 8) ? sh1[l] : 0.f;
        #pragma unroll
        for (int o = 4; o; o >>= 1) {
            s  += __shfl_xor_sync(0xffffffffu, s,  o);
            s2 += __shfl_xor_sync(0xffffffffu, s2, o);
        }
        if (l == 0) { sh0[0] = s; sh1[0] = s2; }
    }
    __syncthreads();
    s = sh0[0]; s2 = sh1[0];
    float mu   = s * (1.0f / EE);
    float var  = s2 * (1.0f / EE) - mu * mu;
    float rstd = rsqrtf(var + LN_EPS);
    size_t base = (size_t)row * EE;
    #pragma unroll
    for (int p = 0; p < 3; p++) {
        int c = tid + p * 256;
        float v = (p == 0) ? v0 : (p == 1) ? v1 : v2;
        float y = (v - mu) * rstd * gamma[c] + beta[c];
        __nv_bfloat16 h = __float2bfloat16(y);
        xh[base + c] = h;
        xl[base + c] = __float2bfloat16(y - __bfloat162float(h));
    }
}

// ---------------- fp32 -> bf16 hi/lo split ----------------
__global__ void __launch_bounds__(256) cvt_kernel(
    const float* __restrict__ w, __nv_bfloat16* __restrict__ hi,
    __nv_bfloat16* __restrict__ lo, int n)
{
    int i = blockIdx.x * 256 + threadIdx.x;
    if (i < n) {
        float v = w[i];
        __nv_bfloat16 h = __float2bfloat16(v);
        hi[i] = h;
        lo[i] = __float2bfloat16(v - __bfloat162float(h));
    }
}

// ---------------- tensor GEMM, cp.async double-buffered + ldmatrix ----------------
// C[m,n] = sum_k A[m,k]*W[n,k] + bias[n]; 128x128 tile; BK=32; 3-pass split bf16.
#define GP 40                              // smem pitch (halves)
#define G_AR   (128*GP)                    // halves per array (5120)
#define G_STG  (4*G_AR)                    // halves per stage  (20480)
#define GEMM_SMEM (2*G_STG*2)              // bytes (81920)
template<int EPI>
__global__ void __launch_bounds__(256, 2) mma_gemm(
    const __nv_bfloat16* __restrict__ Ah, const __nv_bfloat16* __restrict__ Al,
    const __nv_bfloat16* __restrict__ Bh, const __nv_bfloat16* __restrict__ Bl,
    const float* __restrict__ bias, float* __restrict__ C,
    __nv_bfloat16* __restrict__ Pqh, __nv_bfloat16* __restrict__ Pql,
    __nv_bfloat16* __restrict__ Pkh, __nv_bfloat16* __restrict__ Pkl,
    __nv_bfloat16* __restrict__ Pvh, __nv_bfloat16* __restrict__ Pvl,
    int N, int K)
{
    extern __shared__ __align__(16) __nv_bfloat16 gsm[];
    const uint32_t smb = smem_u32(gsm);

    const int tid  = threadIdx.x;
    const int lane = tid & 31;
    const int wid  = tid >> 5;
    const int wm   = (wid >> 2) * 64;
    const int wn   = (wid & 3) * 32;
    const int g    = lane >> 2;
    const int tg   = lane & 3;

    const int m0 = blockIdx.y * 128, n0 = blockIdx.x * 128;
    const int nchunks = K / 32;

    // staging: 2 threads per row; each thread 16 halves (2x 16B) per array
    const int lr = tid >> 1;
    const int lu = (tid & 1) * 16;
    const __nv_bfloat16* pah = Ah + (size_t)(m0 + lr) * K + lu;
    const __nv_bfloat16* pal = Al + (size_t)(m0 + lr) * K + lu;
    const __nv_bfloat16* pbh = Bh + (size_t)(n0 + lr) * K + lu;
    const __nv_bfloat16* pbl = Bl + (size_t)(n0 + lr) * K + lu;
    const uint32_t drow = smb + (lr * GP + lu) * 2;

    auto stage = [&](int c, int s) {
        uint32_t d = drow + s * (G_STG * 2);
        const __nv_bfloat16* a;
        a = pah + c * 32; cp16(d, a);              cp16(d + 16, a + 8);
        a = pal + c * 32; cp16(d + G_AR*2, a);     cp16(d + G_AR*2 + 16, a + 8);
        a = pbh + c * 32; cp16(d + 2*G_AR*2, a);   cp16(d + 2*G_AR*2 + 16, a + 8);
        a = pbl + c * 32; cp16(d + 3*G_AR*2, a);   cp16(d + 3*G_AR*2 + 16, a + 8);
    };

    float acc[4][4][4] = {};

    stage(0, 0);
    CP_COMMIT();

    for (int c = 0; c < nchunks; c++) {
        CP_WAIT0();
        __syncthreads();
        if (c + 1 < nchunks) { stage(c + 1, (c + 1) & 1); CP_COMMIT(); }

        const uint32_t stb = smb + (c & 1) * (G_STG * 2);
        #pragma unroll
        for (int ks = 0; ks < 2; ks++) {
            const int kb = ks * 16;
            uint32_t ah[4][4], al[4][4], bh[4][2], bl[4][2];
            {
                const int arow = (lane & 15);
                const int acol = kb + (lane >> 4) * 8;
                #pragma unroll
                for (int mt = 0; mt < 4; mt++) {
                    uint32_t a = stb + ((wm + mt * 16 + arow) * GP + acol) * 2;
                    ldmx4(ah[mt], a);
                    ldmx4(al[mt], a + G_AR * 2);
                }
            }
            {
                const int brow = (lane & 7) + (lane >> 4) * 8;
                const int bcol = kb + ((lane >> 3) & 1) * 8;
                #pragma unroll
                for (int p = 0; p < 2; p++) {
                    uint32_t a = stb + (2 * G_AR + (wn + p * 16 + brow) * GP + bcol) * 2;
                    uint32_t t[4];
                    ldmx4(t, a);
                    bh[2*p][0] = t[0]; bh[2*p][1] = t[1];
                    bh[2*p+1][0] = t[2]; bh[2*p+1][1] = t[3];
                    ldmx4(t, a + G_AR * 2);
                    bl[2*p][0] = t[0]; bl[2*p][1] = t[1];
                    bl[2*p+1][0] = t[2]; bl[2*p+1][1] = t[3];
                }
            }
            #pragma unroll
            for (int mt = 0; mt < 4; mt++)
                #pragma unroll
                for (int nt = 0; nt < 4; nt++)
                    mma16816(acc[mt][nt][0], acc[mt][nt][1], acc[mt][nt][2], acc[mt][nt][3],
                             ah[mt][0], ah[mt][1], ah[mt][2], ah[mt][3],
                             bh[nt][0], bh[nt][1]);
            #pragma unroll
            for (int mt = 0; mt < 4; mt++)
                #pragma unroll
                for (int nt = 0; nt < 4; nt++)
                    mma16816(acc[mt][nt][0], acc[mt][nt][1], acc[mt][nt][2], acc[mt][nt][3],
                             ah[mt][0], ah[mt][1], ah[mt][2], ah[mt][3],
                             bl[nt][0], bl[nt][1]);
            #pragma unroll
            for (int mt = 0; mt < 4; mt++)
                #pragma unroll
                for (int nt = 0; nt < 4; nt++)
                    mma16816(acc[mt][nt][0], acc[mt][nt][1], acc[mt][nt][2], acc[mt][nt][3],
                             al[mt][0], al[mt][1], al[mt][2], al[mt][3],
                             bh[nt][0], bh[nt][1]);
        }
        __syncthreads();
    }

    #pragma unroll
    for (int mt = 0; mt < 4; mt++) {
        #pragma unroll
        for (int half = 0; half < 2; half++) {
            int m = m0 + wm + mt * 16 + g + half * 8;
            int b_ = m >> 11;
            int s_ = m & 2047;
            #pragma unroll
            for (int nt = 0; nt < 4; nt++) {
                int n = n0 + wn + nt * 8 + 2 * tg;
                float e0 = acc[mt][nt][half*2 + 0] + __ldg(&bias[n]);
                float e1 = acc[mt][nt][half*2 + 1] + __ldg(&bias[n + 1]);
                if (EPI == 1) {
                    *(float2*)&C[(size_t)m * N + n] = make_float2(e0, e1);
                } else {
                    int h_ = n / 192;
                    int rem = n - h_ * 192;
                    int which = rem >> 6;
                    int d0 = rem & 63;
                    __nv_bfloat16* dh = (which == 0) ? Pqh : (which == 1) ? Pkh : Pvh;
                    __nv_bfloat16* dl = (which == 0) ? Pql : (which == 1) ? Pkl : Pvl;
                    size_t base = ((size_t)(b_ * HH + h_) * SS + s_) * HD + d0;
                    __nv_bfloat162 h2 = pack_bf162(e0, e1);
                    __nv_bfloat162 l2 = pack_bf162(e0 - __low2float(h2), e1 - __high2float(h2));
                    *(__nv_bfloat162*)&dh[base] = h2;
                    *(__nv_bfloat162*)&dl[base] = l2;
                }
            }
        }
    }
}

// ---------------- Flash attention, cp.async double-buffered KV + ldmatrix ----------------
// BM=128, BN=64, HD=64; 8 warps x 16 rows; 3-pass split bf16 for QK^T and PV.
// smem (halves): sQh 0, sQl 9216, then 2 KV stages of {Kh,Kl,Vh,Vl} 4608 each.
#define AP 72
#define A_QOFF  (128*AP)        // 9216
#define A_KV0   (2*A_QOFF)      // 18432
#define A_KVSTG (4*64*AP)       // 18432 halves per stage
#define ATT_SMEM ((A_KV0 + 2*A_KVSTG) * 2)   // 110592 bytes
__global__ void __launch_bounds__(256) attn_mma(
    const __nv_bfloat16* __restrict__ qh, const __nv_bfloat16* __restrict__ ql,
    const __nv_bfloat16* __restrict__ kh, const __nv_bfloat16* __restrict__ kl,
    const __nv_bfloat16* __restrict__ vh, const __nv_bfloat16* __restrict__ vl,
    __nv_bfloat16* __restrict__ Oh, __nv_bfloat16* __restrict__ Ol)
{
    extern __shared__ __align__(16) __nv_bfloat16 asm_[];
    const uint32_t smb = smem_u32(asm_);

    const int tid  = threadIdx.x;
    const int lane = tid & 31;
    const int wid  = tid >> 5;
    const int g    = lane >> 2;
    const int tg   = lane & 3;
    const int wm   = wid * 16;

    const int bh = blockIdx.y;
    const int b_ = bh / HH;
    const int h_ = bh - b_ * HH;
    const size_t headoff = (size_t)bh * SS * HD;

    // ---- Q staging via cp.async (plane = tid>>7, row = tid&127) ----
    {
        int row = tid & 127;
        const __nv_bfloat16* src = ((tid < 128) ? qh : ql) + headoff
                                 + (size_t)(blockIdx.x * 128 + row) * HD;
        uint32_t dst = smb + (((tid < 128) ? 0 : A_QOFF) + row * AP) * 2;
        #pragma unroll
        for (int u = 0; u < 8; u++)
            cp16(dst + u * 16, src + u * 8);
    }
    // ---- KV staging lambda (sel = tid>>6: Kh,Kl,Vh,Vl; row = tid&63) ----
    const int sel = tid >> 6;
    const int krow = tid & 63;
    const __nv_bfloat16* ksrc =
        ((sel == 0) ? kh : (sel == 1) ? kl : (sel == 2) ? vh : vl)
        + headoff + (size_t)krow * HD;
    const uint32_t kdst = smb + (A_KV0 + sel * (64*AP) + krow * AP) * 2;

    auto stageKV = [&](int kt, int s) {
        const __nv_bfloat16* src = ksrc + (size_t)(kt * 64) * HD;
        uint32_t dst = kdst + s * (A_KVSTG * 2);
        #pragma unroll
        for (int u = 0; u < 8; u++)
            cp16(dst + u * 16, src + u * 8);
    };

    stageKV(0, 0);
    CP_COMMIT();

    float oacc[8][4] = {};
    float m0_ = -1e30f, m1_ = -1e30f, l0_ = 0.f, l1_ = 0.f;
    const float sc = 0.125f;

    for (int kt = 0; kt < SS / 64; kt++) {
        CP_WAIT0();
        __syncthreads();
        if (kt + 1 < SS / 64) { stageKV(kt + 1, (kt + 1) & 1); CP_COMMIT(); }

        const uint32_t kvb = smb + (A_KV0 + (kt & 1) * A_KVSTG) * 2;

        // ---- S = Q K^T (3-pass) ----
        float sacc[8][4] = {};
        #pragma unroll
        for (int kc = 0; kc < 4; kc++) {
            const int kb = kc * 16;
            uint32_t aqh[4], aql[4], bk[8][2];
            {
                int row = wm + (lane & 15);
                int col = kb + (lane >> 4) * 8;
                uint32_t a = smb + (row * AP + col) * 2;
                ldmx4(aqh, a);
                ldmx4(aql, a + A_QOFF * 2);
            }
            const int brow = (lane & 7) + (lane >> 4) * 8;
            const int bcol = kb + ((lane >> 3) & 1) * 8;
            #pragma unroll
            for (int p = 0; p < 4; p++) {
                uint32_t t[4];
                ldmx4(t, kvb + ((p * 16 + brow) * AP + bcol) * 2);
                bk[2*p][0] = t[0]; bk[2*p][1] = t[1];
                bk[2*p+1][0] = t[2]; bk[2*p+1][1] = t[3];
            }
            #pragma unroll
            for (int nt = 0; nt < 8; nt++)
                mma16816(sacc[nt][0], sacc[nt][1], sacc[nt][2], sacc[nt][3],
                         aqh[0], aqh[1], aqh[2], aqh[3], bk[nt][0], bk[nt][1]);
            #pragma unroll
            for (int nt = 0; nt < 8; nt++)
                mma16816(sacc[nt][0], sacc[nt][1], sacc[nt][2], sacc[nt][3],
                         aql[0], aql[1], aql[2], aql[3], bk[nt][0], bk[nt][1]);
            #pragma unroll
            for (int p = 0; p < 4; p++) {
                uint32_t t[4];
                ldmx4(t, kvb + (64*AP + (p * 16 + brow) * AP + bcol) * 2);
                bk[2*p][0] = t[0]; bk[2*p][1] = t[1];
                bk[2*p+1][0] = t[2]; bk[2*p+1][1] = t[3];
            }
            #pragma unroll
            for (int nt = 0; nt < 8; nt++)
                mma16816(sacc[nt][0], sacc[nt][1], sacc[nt][2], sacc[nt][3],
                         aqh[0], aqh[1], aqh[2], aqh[3], bk[nt][0], bk[nt][1]);
        }

        // ---- online softmax ----
        float rm0 = -1e30f, rm1 = -1e30f;
        #pragma unroll
        for (int nt = 0; nt < 8; nt++) {
            rm0 = fmaxf(rm0, fmaxf(sacc[nt][0], sacc[nt][1]));
            rm1 = fmaxf(rm1, fmaxf(sacc[nt][2], sacc[nt][3]));
        }
        rm0 *= sc; rm1 *= sc;
        rm0 = fmaxf(rm0, __shfl_xor_sync(0xffffffffu, rm0, 1));
        rm0 = fmaxf(rm0, __shfl_xor_sync(0xffffffffu, rm0, 2));
        rm1 = fmaxf(rm1, __shfl_xor_sync(0xffffffffu, rm1, 1));
        rm1 = fmaxf(rm1, __shfl_xor_sync(0xffffffffu, rm1, 2));
        float mn0 = fmaxf(m0_, rm0), mn1 = fmaxf(m1_, rm1);
        float rs0 = 0.f, rs1 = 0.f;
        #pragma unroll
        for (int nt = 0; nt < 8; nt++) {
            sacc[nt][0] = __expf(sacc[nt][0] * sc - mn0);
            sacc[nt][1] = __expf(sacc[nt][1] * sc - mn0);
            sacc[nt][2] = __expf(sacc[nt][2] * sc - mn1);
            sacc[nt][3] = __expf(sacc[nt][3] * sc - mn1);
            rs0 += sacc[nt][0] + sacc[nt][1];
            rs1 += sacc[nt][2] + sacc[nt][3];
        }
        rs0 += __shfl_xor_sync(0xffffffffu, rs0, 1);
        rs0 += __shfl_xor_sync(0xffffffffu, rs0, 2);
        rs1 += __shfl_xor_sync(0xffffffffu, rs1, 1);
        rs1 += __shfl_xor_sync(0xffffffffu, rs1, 2);
        float al0 = __expf(m0_ - mn0), al1 = __expf(m1_ - mn1);
        l0_ = l0_ * al0 + rs0;  m0_ = mn0;
        l1_ = l1_ * al1 + rs1;  m1_ = mn1;
        #pragma unroll
        for (int nt = 0; nt < 8; nt++) {
            oacc[nt][0] *= al0; oacc[nt][1] *= al0;
            oacc[nt][2] *= al1; oacc[nt][3] *= al1;
        }

        // ---- pack P fragments (hi + lo) in registers ----
        uint32_t ph[4][4], pl[4][4];
        #pragma unroll
        for (int kc = 0; kc < 4; kc++) {
            __nv_bfloat162 h0 = pack_bf162(sacc[2*kc][0],   sacc[2*kc][1]);
            __nv_bfloat162 h1 = pack_bf162(sacc[2*kc][2],   sacc[2*kc][3]);
            __nv_bfloat162 h2 = pack_bf162(sacc[2*kc+1][0], sacc[2*kc+1][1]);
            __nv_bfloat162 h3 = pack_bf162(sacc[2*kc+1][2], sacc[2*kc+1][3]);
            ph[kc][0] = *(uint32_t*)&h0; ph[kc][1] = *(uint32_t*)&h1;
            ph[kc][2] = *(uint32_t*)&h2; ph[kc][3] = *(uint32_t*)&h3;
            __nv_bfloat162 q0 = pack_bf162(sacc[2*kc][0]   - __low2float(h0), sacc[2*kc][1]   - __high2float(h0));
            __nv_bfloat162 q1 = pack_bf162(sacc[2*kc][2]   - __low2float(h1), sacc[2*kc][3]   - __high2float(h1));
            __nv_bfloat162 q2 = pack_bf162(sacc[2*kc+1][0] - __low2float(h2), sacc[2*kc+1][1] - __high2float(h2));
            __nv_bfloat162 q3 = pack_bf162(sacc[2*kc+1][2] - __low2float(h3), sacc[2*kc+1][3] - __high2float(h3));
            pl[kc][0] = *(uint32_t*)&q0; pl[kc][1] = *(uint32_t*)&q1;
            pl[kc][2] = *(uint32_t*)&q2; pl[kc][3] = *(uint32_t*)&q3;
        }

        // ---- O += P V (3-pass), V via ldmatrix.trans from [kv][d] layout ----
        #pragma unroll
        for (int kc = 0; kc < 4; kc++) {
            const int kb = kc * 16;
            uint32_t bv[8][2];
            const int vrow = kb + ((lane >> 3) & 1) * 8 + (lane & 7);
            const int vcol = (lane >> 4) * 8;
            #pragma unroll
            for (int p = 0; p < 4; p++) {
                uint32_t t[4];
                ldmx4t(t, kvb + (2*64*AP + vrow * AP + p * 16 + vcol) * 2);
                bv[2*p][0] = t[0]; bv[2*p][1] = t[1];
                bv[2*p+1][0] = t[2]; bv[2*p+1][1] = t[3];
            }
            #pragma unroll
            for (int nt = 0; nt < 8; nt++)
                mma16816(oacc[nt][0], oacc[nt][1], oacc[nt][2], oacc[nt][3],
                         ph[kc][0], ph[kc][1], ph[kc][2], ph[kc][3], bv[nt][0], bv[nt][1]);
            #pragma unroll
            for (int nt = 0; nt < 8; nt++)
                mma16816(oacc[nt][0], oacc[nt][1], oacc[nt][2], oacc[nt][3],
                         pl[kc][0], pl[kc][1], pl[kc][2], pl[kc][3], bv[nt][0], bv[nt][1]);
            #pragma unroll
            for (int p = 0; p < 4; p++) {
                uint32_t t[4];
                ldmx4t(t, kvb + (3*64*AP + vrow * AP + p * 16 + vcol) * 2);
                bv[2*p][0] = t[0]; bv[2*p][1] = t[1];
                bv[2*p+1][0] = t[2]; bv[2*p+1][1] = t[3];
            }
            #pragma unroll
            for (int nt = 0; nt < 8; nt++)
                mma16816(oacc[nt][0], oacc[nt][1], oacc[nt][2], oacc[nt][3],
                         ph[kc][0], ph[kc][1], ph[kc][2], ph[kc][3], bv[nt][0], bv[nt][1]);
        }
        __syncthreads();
    }

    // ---- epilogue ----
    float inv0 = 1.0f / l0_, inv1 = 1.0f / l1_;
    int sbase = blockIdx.x * 128 + wm;
    size_t ob0 = ((size_t)(b_ * SS + sbase + g))     * EE + h_ * HD + 2 * tg;
    size_t ob1 = ((size_t)(b_ * SS + sbase + g + 8)) * EE + h_ * HD + 2 * tg;
    #pragma unroll
    for (int nt = 0; nt < 8; nt++) {
        int d = nt * 8;
        float e0 = oacc[nt][0] * inv0, e1 = oacc[nt][1] * inv0;
        __nv_bfloat162 h2 = pack_bf162(e0, e1);
        __nv_bfloat162 l2 = pack_bf162(e0 - __low2float(h2), e1 - __high2float(h2));
        *(__nv_bfloat162*)&Oh[ob0 + d] = h2;
        *(__nv_bfloat162*)&Ol[ob0 + d] = l2;
        e0 = oacc[nt][2] * inv1; e1 = oacc[nt][3] * inv1;
        h2 = pack_bf162(e0, e1);
        l2 = pack_bf162(e0 - __low2float(h2), e1 - __high2float(h2));
        *(__nv_bfloat162*)&Oh[ob1 + d] = h2;
        *(__nv_bfloat162*)&Ol[ob1 + d] = l2;
    }
}

// ---------------- launch ----------------
extern "C" void kernel_launch(void* const* d_in, const int* in_sizes, int n_in,
                              void* d_out, int out_size)
{
    const float* x     = (const float*)d_in[0];
    const float* gamma = (const float*)d_in[1];
    const float* beta  = (const float*)d_in[2];
    const float* Wqkv  = (const float*)d_in[3];
    const float* bqkv  = (const float*)d_in[4];
    const float* Wo    = (const float*)d_in[5];
    const float* bo    = (const float*)d_in[6];
    float* out = (float*)d_out;

    __nv_bfloat16 *xh, *xl, *wqh, *wql, *woh, *wol, *oh, *ol;
    __nv_bfloat16 *qh, *ql, *kh, *kl, *vh, *vl;
    cudaGetSymbolAddress((void**)&xh,  g_xh);
    cudaGetSymbolAddress((void**)&xl,  g_xl);
    cudaGetSymbolAddress((void**)&wqh, g_wqh);
    cudaGetSymbolAddress((void**)&wql, g_wql);
    cudaGetSymbolAddress((void**)&woh, g_woh);
    cudaGetSymbolAddress((void**)&wol, g_wol);
    cudaGetSymbolAddress((void**)&qh,  g_qh);
    cudaGetSymbolAddress((void**)&ql,  g_ql);
    cudaGetSymbolAddress((void**)&kh,  g_kh);
    cudaGetSymbolAddress((void**)&kl,  g_kl);
    cudaGetSymbolAddress((void**)&vh,  g_vh);
    cudaGetSymbolAddress((void**)&vl,  g_vl);
    cudaGetSymbolAddress((void**)&oh,  g_oh);
    cudaGetSymbolAddress((void**)&ol,  g_ol);

    cudaFuncSetAttribute(attn_mma,    cudaFuncAttributeMaxDynamicSharedMemorySize, ATT_SMEM);
    cudaFuncSetAttribute(mma_gemm<0>, cudaFuncAttributeMaxDynamicSharedMemorySize, GEMM_SMEM);
    cudaFuncSetAttribute(mma_gemm<1>, cudaFuncAttributeMaxDynamicSharedMemorySize, GEMM_SMEM);

    ln_kernel<<<MROWS, 256>>>(x, gamma, beta, xh, xl);
    cvt_kernel<<<(NQKV*EE + 255)/256, 256>>>(Wqkv, wqh, wql, NQKV*EE);
    cvt_kernel<<<(EE*EE   + 255)/256, 256>>>(Wo,   woh, wol, EE*EE);

    mma_gemm<0><<<dim3(NQKV/128, MROWS/128), 256, GEMM_SMEM>>>(
        xh, xl, wqh, wql, bqkv, nullptr, qh, ql, kh, kl, vh, vl, NQKV, EE);

    attn_mma<<<dim3(SS/128, BB*HH), 256, ATT_SMEM>>>(qh, ql, kh, kl, vh, vl, oh, ol);

    mma_gemm<1><<<dim3(EE/128, MROWS/128), 256, GEMM_SMEM>>>(
        oh, ol, woh, wol, bo, out, nullptr, nullptr, nullptr, nullptr, nullptr, nullptr, EE, EE);
}

// round 7
// speedup vs baseline: 12.8574x; 1.1918x over previous
#include <cuda_runtime.h>
#include <cuda_fp16.h>
#include <math.h>
#include <cstdint>

#define BB 2
#define SS 2048
#define EE 768
#define HH 12
#define HD 64
#define MROWS (BB*SS)          // 4096
#define NQKV (3*EE)            // 2304
#define LN_EPS 1e-5f

// ---------------- scratch (no allocations allowed) ----------------
__device__ __align__(16) __half g_xh[MROWS*EE];
__device__ __align__(16) __half g_xl[MROWS*EE];
__device__ __align__(16) __half g_wqh[NQKV*EE];
__device__ __align__(16) __half g_wql[NQKV*EE];
__device__ __align__(16) __half g_woh[EE*EE];
__device__ __align__(16) __half g_wol[EE*EE];
__device__ __align__(16) __half g_qh[BB*HH*SS*HD];
__device__ __align__(16) __half g_ql[BB*HH*SS*HD];
__device__ __align__(16) __half g_kh[BB*HH*SS*HD];
__device__ __align__(16) __half g_vh[BB*HH*SS*HD];
__device__ __align__(16) __half g_vl[BB*HH*SS*HD];
__device__ __align__(16) __half g_oh[MROWS*EE];
__device__ __align__(16) __half g_ol[MROWS*EE];

// ================= helpers =================
__device__ __forceinline__ uint32_t smem_u32(const void* p) {
    uint32_t a;
    asm("{ .reg .u64 t; cvta.to.shared.u64 t, %1; cvt.u32.u64 %0, t; }" : "=r"(a) : "l"(p));
    return a;
}
__device__ __forceinline__ void cp16(uint32_t dst, const void* src) {
    asm volatile("cp.async.cg.shared.global [%0], [%1], 16;" :: "r"(dst), "l"(src));
}
#define CP_COMMIT() asm volatile("cp.async.commit_group;" ::: "memory")
#define CP_WAIT0()  asm volatile("cp.async.wait_group 0;" ::: "memory")

__device__ __forceinline__ void ldmx4(uint32_t* r, uint32_t a) {
    asm volatile("ldmatrix.sync.aligned.m8n8.x4.shared.b16 {%0,%1,%2,%3}, [%4];"
        : "=r"(r[0]), "=r"(r[1]), "=r"(r[2]), "=r"(r[3]) : "r"(a));
}
__device__ __forceinline__ void ldmx4t(uint32_t* r, uint32_t a) {
    asm volatile("ldmatrix.sync.aligned.m8n8.x4.trans.shared.b16 {%0,%1,%2,%3}, [%4];"
        : "=r"(r[0]), "=r"(r[1]), "=r"(r[2]), "=r"(r[3]) : "r"(a));
}
__device__ __forceinline__ void mma16816(
    float& c0, float& c1, float& c2, float& c3,
    uint32_t a0, uint32_t a1, uint32_t a2, uint32_t a3,
    uint32_t b0, uint32_t b1)
{
    asm volatile(
        "mma.sync.aligned.m16n8k16.row.col.f32.f16.f16.f32 "
        "{%0,%1,%2,%3}, {%4,%5,%6,%7}, {%8,%9}, {%0,%1,%2,%3};"
        : "+f"(c0), "+f"(c1), "+f"(c2), "+f"(c3)
        : "r"(a0), "r"(a1), "r"(a2), "r"(a3), "r"(b0), "r"(b1));
}
__device__ __forceinline__ uint32_t pack_h2(float a, float b) {
    __half2 t = __floats2half2_rn(a, b);
    return *(uint32_t*)&t;
}

// ---------------- LayerNorm ----------------
__global__ void __launch_bounds__(256) ln_kernel(
    const float* __restrict__ x, const float* __restrict__ gamma,
    const float* __restrict__ beta, __half* __restrict__ xh,
    __half* __restrict__ xl)
{
    int row = blockIdx.x;
    int tid = threadIdx.x;
    const float* xr = x + (size_t)row * EE;
    float v0 = xr[tid], v1 = xr[tid+256], v2 = xr[tid+512];
    float s  = v0 + v1 + v2;
    float s2 = v0*v0 + v1*v1 + v2*v2;
    #pragma unroll
    for (int o = 16; o; o >>= 1) {
        s  += __shfl_xor_sync(0xffffffffu, s,  o);
        s2 += __shfl_xor_sync(0xffffffffu, s2, o);
    }
    __shared__ float sh0[8], sh1[8];
    int w = tid >> 5, l = tid & 31;
    if (l == 0) { sh0[w] = s; sh1[w] = s2; }
    __syncthreads();
    if (tid < 32) {
        s  = (l < 8) ? sh0[l] : 0.f;
        s2 = (l < 8) ? sh1[l] : 0.f;
        #pragma unroll
        for (int o = 4; o; o >>= 1) {
            s  += __shfl_xor_sync(0xffffffffu, s,  o);
            s2 += __shfl_xor_sync(0xffffffffu, s2, o);
        }
        if (l == 0) { sh0[0] = s; sh1[0] = s2; }
    }
    __syncthreads();
    s = sh0[0]; s2 = sh1[0];
    float mu   = s * (1.0f / EE);
    float var  = s2 * (1.0f / EE) - mu * mu;
    float rstd = rsqrtf(var + LN_EPS);
    size_t base = (size_t)row * EE;
    #pragma unroll
    for (int p = 0; p < 3; p++) {
        int c = tid + p * 256;
        float v = (p == 0) ? v0 : (p == 1) ? v1 : v2;
        float y = (v - mu) * rstd * gamma[c] + beta[c];
        __half h = __float2half_rn(y);
        xh[base + c] = h;
        xl[base + c] = __float2half_rn(y - __half2float(h));
    }
}

// ---------------- fp32 -> fp16 hi/lo split ----------------
__global__ void __launch_bounds__(256) cvt_kernel(
    const float* __restrict__ w, __half* __restrict__ hi,
    __half* __restrict__ lo, int n)
{
    int i = blockIdx.x * 256 + threadIdx.x;
    if (i < n) {
        float v = w[i];
        __half h = __float2half_rn(v);
        hi[i] = h;
        lo[i] = __float2half_rn(v - __half2float(h));
    }
}

// ---------------- tensor GEMM, cp.async double-buffered + ldmatrix ----------------
// C[m,n] = sum_k A[m,k]*W[n,k] + bias[n]; 128x128 tile; BK=32; 3-pass split fp16.
#define GP 40
#define G_AR   (128*GP)
#define G_STG  (4*G_AR)
#define GEMM_SMEM (2*G_STG*2)
template<int EPI>
__global__ void __launch_bounds__(256, 2) mma_gemm(
    const __half* __restrict__ Ah, const __half* __restrict__ Al,
    const __half* __restrict__ Bh, const __half* __restrict__ Bl,
    const float* __restrict__ bias, float* __restrict__ C,
    __half* __restrict__ Pqh, __half* __restrict__ Pql,
    __half* __restrict__ Pkh,
    __half* __restrict__ Pvh, __half* __restrict__ Pvl,
    int N, int K)
{
    extern __shared__ __align__(16) __half gsm[];
    const uint32_t smb = smem_u32(gsm);

    const int tid  = threadIdx.x;
    const int lane = tid & 31;
    const int wid  = tid >> 5;
    const int wm   = (wid >> 2) * 64;
    const int wn   = (wid & 3) * 32;
    const int g    = lane >> 2;
    const int tg   = lane & 3;

    const int m0 = blockIdx.y * 128, n0 = blockIdx.x * 128;
    const int nchunks = K / 32;

    const int lr = tid >> 1;
    const int lu = (tid & 1) * 16;
    const __half* pah = Ah + (size_t)(m0 + lr) * K + lu;
    const __half* pal = Al + (size_t)(m0 + lr) * K + lu;
    const __half* pbh = Bh + (size_t)(n0 + lr) * K + lu;
    const __half* pbl = Bl + (size_t)(n0 + lr) * K + lu;
    const uint32_t drow = smb + (lr * GP + lu) * 2;

    auto stage = [&](int c, int s) {
        uint32_t d = drow + s * (G_STG * 2);
        const __half* a;
        a = pah + c * 32; cp16(d, a);              cp16(d + 16, a + 8);
        a = pal + c * 32; cp16(d + G_AR*2, a);     cp16(d + G_AR*2 + 16, a + 8);
        a = pbh + c * 32; cp16(d + 2*G_AR*2, a);   cp16(d + 2*G_AR*2 + 16, a + 8);
        a = pbl + c * 32; cp16(d + 3*G_AR*2, a);   cp16(d + 3*G_AR*2 + 16, a + 8);
    };

    float acc[4][4][4] = {};

    stage(0, 0);
    CP_COMMIT();

    for (int c = 0; c < nchunks; c++) {
        CP_WAIT0();
        __syncthreads();
        if (c + 1 < nchunks) { stage(c + 1, (c + 1) & 1); CP_COMMIT(); }

        const uint32_t stb = smb + (c & 1) * (G_STG * 2);
        #pragma unroll
        for (int ks = 0; ks < 2; ks++) {
            const int kb = ks * 16;
            uint32_t ah[4][4], al[4][4], bh[4][2], bl[4][2];
            {
                const int arow = (lane & 15);
                const int acol = kb + (lane >> 4) * 8;
                #pragma unroll
                for (int mt = 0; mt < 4; mt++) {
                    uint32_t a = stb + ((wm + mt * 16 + arow) * GP + acol) * 2;
                    ldmx4(ah[mt], a);
                    ldmx4(al[mt], a + G_AR * 2);
                }
            }
            {
                const int brow = (lane & 7) + (lane >> 4) * 8;
                const int bcol = kb + ((lane >> 3) & 1) * 8;
                #pragma unroll
                for (int p = 0; p < 2; p++) {
                    uint32_t a = stb + (2 * G_AR + (wn + p * 16 + brow) * GP + bcol) * 2;
                    uint32_t t[4];
                    ldmx4(t, a);
                    bh[2*p][0] = t[0]; bh[2*p][1] = t[1];
                    bh[2*p+1][0] = t[2]; bh[2*p+1][1] = t[3];
                    ldmx4(t, a + G_AR * 2);
                    bl[2*p][0] = t[0]; bl[2*p][1] = t[1];
                    bl[2*p+1][0] = t[2]; bl[2*p+1][1] = t[3];
                }
            }
            #pragma unroll
            for (int mt = 0; mt < 4; mt++)
                #pragma unroll
                for (int nt = 0; nt < 4; nt++)
                    mma16816(acc[mt][nt][0], acc[mt][nt][1], acc[mt][nt][2], acc[mt][nt][3],
                             ah[mt][0], ah[mt][1], ah[mt][2], ah[mt][3],
                             bh[nt][0], bh[nt][1]);
            #pragma unroll
            for (int mt = 0; mt < 4; mt++)
                #pragma unroll
                for (int nt = 0; nt < 4; nt++)
                    mma16816(acc[mt][nt][0], acc[mt][nt][1], acc[mt][nt][2], acc[mt][nt][3],
                             ah[mt][0], ah[mt][1], ah[mt][2], ah[mt][3],
                             bl[nt][0], bl[nt][1]);
            #pragma unroll
            for (int mt = 0; mt < 4; mt++)
                #pragma unroll
                for (int nt = 0; nt < 4; nt++)
                    mma16816(acc[mt][nt][0], acc[mt][nt][1], acc[mt][nt][2], acc[mt][nt][3],
                             al[mt][0], al[mt][1], al[mt][2], al[mt][3],
                             bh[nt][0], bh[nt][1]);
        }
        __syncthreads();
    }

    #pragma unroll
    for (int mt = 0; mt < 4; mt++) {
        #pragma unroll
        for (int half = 0; half < 2; half++) {
            int m = m0 + wm + mt * 16 + g + half * 8;
            int b_ = m >> 11;
            int s_ = m & 2047;
            #pragma unroll
            for (int nt = 0; nt < 4; nt++) {
                int n = n0 + wn + nt * 8 + 2 * tg;
                float e0 = acc[mt][nt][half*2 + 0] + __ldg(&bias[n]);
                float e1 = acc[mt][nt][half*2 + 1] + __ldg(&bias[n + 1]);
                if (EPI == 1) {
                    *(float2*)&C[(size_t)m * N + n] = make_float2(e0, e1);
                } else {
                    int h_ = n / 192;
                    int rem = n - h_ * 192;
                    int which = rem >> 6;
                    int d0 = rem & 63;
                    size_t base = ((size_t)(b_ * HH + h_) * SS + s_) * HD + d0;
                    uint32_t h2 = pack_h2(e0, e1);
                    if (which == 1) {
                        *(uint32_t*)&Pkh[base] = h2;
                    } else {
                        __half2 hv = *(__half2*)&h2;
                        uint32_t l2 = pack_h2(e0 - __low2float(hv), e1 - __high2float(hv));
                        __half* dh = (which == 0) ? Pqh : Pvh;
                        __half* dl = (which == 0) ? Pql : Pvl;
                        *(uint32_t*)&dh[base] = h2;
                        *(uint32_t*)&dl[base] = l2;
                    }
                }
            }
        }
    }
}

// ---------------- Flash attention, fp16 2-pass, cp.async KV + ldmatrix ----------------
// BM=128, BN=64, HD=64; 8 warps x 16 rows.
// S = (Qh+Ql)·Kh^T (2 passes); O += Ph·(Vh+Vl) (2 passes).
#define AP 72
#define A_QOFF  (128*AP)          // halves
#define A_KV0   (2*A_QOFF)        // 18432 halves
#define A_KVSTG (3*64*AP)         // 13824 halves per stage {Kh,Vh,Vl}
#define ATT_SMEM ((A_KV0 + 2*A_KVSTG) * 2)   // 92160 bytes
__global__ void __launch_bounds__(256) attn_mma(
    const __half* __restrict__ qh, const __half* __restrict__ ql,
    const __half* __restrict__ kh,
    const __half* __restrict__ vh, const __half* __restrict__ vl,
    __half* __restrict__ Oh, __half* __restrict__ Ol)
{
    extern __shared__ __align__(16) __half asm_[];
    const uint32_t smb = smem_u32(asm_);

    const int tid  = threadIdx.x;
    const int lane = tid & 31;
    const int wid  = tid >> 5;
    const int g    = lane >> 2;
    const int tg   = lane & 3;
    const int wm   = wid * 16;

    const int bh = blockIdx.y;
    const int b_ = bh / HH;
    const int h_ = bh - b_ * HH;
    const size_t headoff = (size_t)bh * SS * HD;

    // ---- Q staging (plane = tid>>7, row = tid&127) ----
    {
        int row = tid & 127;
        const __half* src = ((tid < 128) ? qh : ql) + headoff
                          + (size_t)(blockIdx.x * 128 + row) * HD;
        uint32_t dst = smb + (((tid < 128) ? 0 : A_QOFF) + row * AP) * 2;
        #pragma unroll
        for (int u = 0; u < 8; u++)
            cp16(dst + u * 16, src + u * 8);
    }
    // ---- KV staging: 192 active threads; sel 0=Kh,1=Vh,2=Vl; row = tid&63 ----
    const int sel = tid >> 6;          // 0..3
    const int krow = tid & 63;
    const __half* ksrc =
        ((sel == 0) ? kh : (sel == 1) ? vh : vl) + headoff + (size_t)krow * HD;
    const uint32_t kdst = smb + (A_KV0 + sel * (64*AP) + krow * AP) * 2;

    auto stageKV = [&](int kt, int s) {
        if (sel < 3) {
            const __half* src = ksrc + (size_t)(kt * 64) * HD;
            uint32_t dst = kdst + s * (A_KVSTG * 2);
            #pragma unroll
            for (int u = 0; u < 8; u++)
                cp16(dst + u * 16, src + u * 8);
        }
    };

    stageKV(0, 0);
    CP_COMMIT();

    float oacc[8][4] = {};
    float m0_ = -1e30f, m1_ = -1e30f, l0_ = 0.f, l1_ = 0.f;
    const float sc = 0.125f;

    for (int kt = 0; kt < SS / 64; kt++) {
        CP_WAIT0();
        __syncthreads();
        if (kt + 1 < SS / 64) { stageKV(kt + 1, (kt + 1) & 1); CP_COMMIT(); }

        const uint32_t kvb = smb + (A_KV0 + (kt & 1) * A_KVSTG) * 2;

        // ---- S = Q Kh^T (2-pass: Qh, Ql) ----
        float sacc[8][4] = {};
        #pragma unroll
        for (int kc = 0; kc < 4; kc++) {
            const int kb = kc * 16;
            uint32_t aqh[4], aql[4], bk[8][2];
            {
                int row = wm + (lane & 15);
                int col = kb + (lane >> 4) * 8;
                uint32_t a = smb + (row * AP + col) * 2;
                ldmx4(aqh, a);
                ldmx4(aql, a + A_QOFF * 2);
            }
            const int brow = (lane & 7) + (lane >> 4) * 8;
            const int bcol = kb + ((lane >> 3) & 1) * 8;
            #pragma unroll
            for (int p = 0; p < 4; p++) {
                uint32_t t[4];
                ldmx4(t, kvb + ((p * 16 + brow) * AP + bcol) * 2);
                bk[2*p][0] = t[0]; bk[2*p][1] = t[1];
                bk[2*p+1][0] = t[2]; bk[2*p+1][1] = t[3];
            }
            #pragma unroll
            for (int nt = 0; nt < 8; nt++)
                mma16816(sacc[nt][0], sacc[nt][1], sacc[nt][2], sacc[nt][3],
                         aqh[0], aqh[1], aqh[2], aqh[3], bk[nt][0], bk[nt][1]);
            #pragma unroll
            for (int nt = 0; nt < 8; nt++)
                mma16816(sacc[nt][0], sacc[nt][1], sacc[nt][2], sacc[nt][3],
                         aql[0], aql[1], aql[2], aql[3], bk[nt][0], bk[nt][1]);
        }

        // ---- online softmax ----
        float rm0 = -1e30f, rm1 = -1e30f;
        #pragma unroll
        for (int nt = 0; nt < 8; nt++) {
            rm0 = fmaxf(rm0, fmaxf(sacc[nt][0], sacc[nt][1]));
            rm1 = fmaxf(rm1, fmaxf(sacc[nt][2], sacc[nt][3]));
        }
        rm0 *= sc; rm1 *= sc;
        rm0 = fmaxf(rm0, __shfl_xor_sync(0xffffffffu, rm0, 1));
        rm0 = fmaxf(rm0, __shfl_xor_sync(0xffffffffu, rm0, 2));
        rm1 = fmaxf(rm1, __shfl_xor_sync(0xffffffffu, rm1, 1));
        rm1 = fmaxf(rm1, __shfl_xor_sync(0xffffffffu, rm1, 2));
        float mn0 = fmaxf(m0_, rm0), mn1 = fmaxf(m1_, rm1);
        float rs0 = 0.f, rs1 = 0.f;
        #pragma unroll
        for (int nt = 0; nt < 8; nt++) {
            sacc[nt][0] = __expf(sacc[nt][0] * sc - mn0);
            sacc[nt][1] = __expf(sacc[nt][1] * sc - mn0);
            sacc[nt][2] = __expf(sacc[nt][2] * sc - mn1);
            sacc[nt][3] = __expf(sacc[nt][3] * sc - mn1);
            rs0 += sacc[nt][0] + sacc[nt][1];
            rs1 += sacc[nt][2] + sacc[nt][3];
        }
        rs0 += __shfl_xor_sync(0xffffffffu, rs0, 1);
        rs0 += __shfl_xor_sync(0xffffffffu, rs0, 2);
        rs1 += __shfl_xor_sync(0xffffffffu, rs1, 1);
        rs1 += __shfl_xor_sync(0xffffffffu, rs1, 2);
        float al0 = __expf(m0_ - mn0), al1 = __expf(m1_ - mn1);
        l0_ = l0_ * al0 + rs0;  m0_ = mn0;
        l1_ = l1_ * al1 + rs1;  m1_ = mn1;
        #pragma unroll
        for (int nt = 0; nt < 8; nt++) {
            oacc[nt][0] *= al0; oacc[nt][1] *= al0;
            oacc[nt][2] *= al1; oacc[nt][3] *= al1;
        }

        // ---- pack P fragments (hi only) ----
        uint32_t ph[4][4];
        #pragma unroll
        for (int kc = 0; kc < 4; kc++) {
            ph[kc][0] = pack_h2(sacc[2*kc][0],   sacc[2*kc][1]);
            ph[kc][1] = pack_h2(sacc[2*kc][2],   sacc[2*kc][3]);
            ph[kc][2] = pack_h2(sacc[2*kc+1][0], sacc[2*kc+1][1]);
            ph[kc][3] = pack_h2(sacc[2*kc+1][2], sacc[2*kc+1][3]);
        }

        // ---- O += Ph (Vh + Vl), V via ldmatrix.trans ----
        #pragma unroll
        for (int kc = 0; kc < 4; kc++) {
            const int kb = kc * 16;
            uint32_t bv[8][2];
            const int vrow = kb + ((lane >> 3) & 1) * 8 + (lane & 7);
            const int vcol = (lane >> 4) * 8;
            #pragma unroll
            for (int p = 0; p < 4; p++) {
                uint32_t t[4];
                ldmx4t(t, kvb + (64*AP + vrow * AP + p * 16 + vcol) * 2);
                bv[2*p][0] = t[0]; bv[2*p][1] = t[1];
                bv[2*p+1][0] = t[2]; bv[2*p+1][1] = t[3];
            }
            #pragma unroll
            for (int nt = 0; nt < 8; nt++)
                mma16816(oacc[nt][0], oacc[nt][1], oacc[nt][2], oacc[nt][3],
                         ph[kc][0], ph[kc][1], ph[kc][2], ph[kc][3], bv[nt][0], bv[nt][1]);
            #pragma unroll
            for (int p = 0; p < 4; p++) {
                uint32_t t[4];
                ldmx4t(t, kvb + (2*64*AP + vrow * AP + p * 16 + vcol) * 2);
                bv[2*p][0] = t[0]; bv[2*p][1] = t[1];
                bv[2*p+1][0] = t[2]; bv[2*p+1][1] = t[3];
            }
            #pragma unroll
            for (int nt = 0; nt < 8; nt++)
                mma16816(oacc[nt][0], oacc[nt][1], oacc[nt][2], oacc[nt][3],
                         ph[kc][0], ph[kc][1], ph[kc][2], ph[kc][3], bv[nt][0], bv[nt][1]);
        }
        __syncthreads();
    }

    // ---- epilogue ----
    float inv0 = 1.0f / l0_, inv1 = 1.0f / l1_;
    int sbase = blockIdx.x * 128 + wm;
    size_t ob0 = ((size_t)(b_ * SS + sbase + g))     * EE + h_ * HD + 2 * tg;
    size_t ob1 = ((size_t)(b_ * SS + sbase + g + 8)) * EE + h_ * HD + 2 * tg;
    #pragma unroll
    for (int nt = 0; nt < 8; nt++) {
        int d = nt * 8;
        float e0 = oacc[nt][0] * inv0, e1 = oacc[nt][1] * inv0;
        uint32_t h2 = pack_h2(e0, e1);
        __half2 hv = *(__half2*)&h2;
        uint32_t l2 = pack_h2(e0 - __low2float(hv), e1 - __high2float(hv));
        *(uint32_t*)&Oh[ob0 + d] = h2;
        *(uint32_t*)&Ol[ob0 + d] = l2;
        e0 = oacc[nt][2] * inv1; e1 = oacc[nt][3] * inv1;
        h2 = pack_h2(e0, e1);
        hv = *(__half2*)&h2;
        l2 = pack_h2(e0 - __low2float(hv), e1 - __high2float(hv));
        *(uint32_t*)&Oh[ob1 + d] = h2;
        *(uint32_t*)&Ol[ob1 + d] = l2;
    }
}

// ---------------- launch ----------------
extern "C" void kernel_launch(void* const* d_in, const int* in_sizes, int n_in,
                              void* d_out, int out_size)
{
    const float* x     = (const float*)d_in[0];
    const float* gamma = (const float*)d_in[1];
    const float* beta  = (const float*)d_in[2];
    const float* Wqkv  = (const float*)d_in[3];
    const float* bqkv  = (const float*)d_in[4];
    const float* Wo    = (const float*)d_in[5];
    const float* bo    = (const float*)d_in[6];
    float* out = (float*)d_out;

    __half *xh, *xl, *wqh, *wql, *woh, *wol, *oh, *ol;
    __half *qh, *ql, *kh, *vh, *vl;
    cudaGetSymbolAddress((void**)&xh,  g_xh);
    cudaGetSymbolAddress((void**)&xl,  g_xl);
    cudaGetSymbolAddress((void**)&wqh, g_wqh);
    cudaGetSymbolAddress((void**)&wql, g_wql);
    cudaGetSymbolAddress((void**)&woh, g_woh);
    cudaGetSymbolAddress((void**)&wol, g_wol);
    cudaGetSymbolAddress((void**)&qh,  g_qh);
    cudaGetSymbolAddress((void**)&ql,  g_ql);
    cudaGetSymbolAddress((void**)&kh,  g_kh);
    cudaGetSymbolAddress((void**)&vh,  g_vh);
    cudaGetSymbolAddress((void**)&vl,  g_vl);
    cudaGetSymbolAddress((void**)&oh,  g_oh);
    cudaGetSymbolAddress((void**)&ol,  g_ol);

    cudaFuncSetAttribute(attn_mma,    cudaFuncAttributeMaxDynamicSharedMemorySize, ATT_SMEM);
    cudaFuncSetAttribute(mma_gemm<0>, cudaFuncAttributeMaxDynamicSharedMemorySize, GEMM_SMEM);
    cudaFuncSetAttribute(mma_gemm<1>, cudaFuncAttributeMaxDynamicSharedMemorySize, GEMM_SMEM);

    ln_kernel<<<MROWS, 256>>>(x, gamma, beta, xh, xl);
    cvt_kernel<<<(NQKV*EE + 255)/256, 256>>>(Wqkv, wqh, wql, NQKV*EE);
    cvt_kernel<<<(EE*EE   + 255)/256, 256>>>(Wo,   woh, wol, EE*EE);

    mma_gemm<0><<<dim3(NQKV/128, MROWS/128), 256, GEMM_SMEM>>>(
        xh, xl, wqh, wql, bqkv, nullptr, qh, ql, kh, vh, vl, NQKV, EE);

    attn_mma<<<dim3(SS/128, BB*HH), 256, ATT_SMEM>>>(qh, ql, kh, vh, vl, oh, ol);

    mma_gemm<1><<<dim3(EE/128, MROWS/128), 256, GEMM_SMEM>>>(
        oh, ol, woh, wol, bo, out, nullptr, nullptr, nullptr, nullptr, nullptr, EE, EE);
}

// round 8
// speedup vs baseline: 17.1312x; 1.3324x over previous
#include <cuda_runtime.h>
#include <cuda_fp16.h>
#include <math.h>
#include <cstdint>

#define BB 2
#define SS 2048
#define EE 768
#define HH 12
#define HD 64
#define MROWS (BB*SS)          // 4096
#define NQKV (3*EE)            // 2304
#define LN_EPS 1e-5f

// ---------------- scratch (no allocations allowed) ----------------
__device__ __align__(16) __half g_xh[MROWS*EE];
__device__ __align__(16) __half g_xl[MROWS*EE];
__device__ __align__(16) __half g_wqh[NQKV*EE];
__device__ __align__(16) __half g_woh[EE*EE];
__device__ __align__(16) __half g_qh[BB*HH*SS*HD];
__device__ __align__(16) __half g_ql[BB*HH*SS*HD];
__device__ __align__(16) __half g_kh[BB*HH*SS*HD];
__device__ __align__(16) __half g_vh[BB*HH*SS*HD];
__device__ __align__(16) __half g_oh[MROWS*EE];
__device__ __align__(16) __half g_ol[MROWS*EE];

// ================= helpers =================
__device__ __forceinline__ uint32_t smem_u32(const void* p) {
    uint32_t a;
    asm("{ .reg .u64 t; cvta.to.shared.u64 t, %1; cvt.u32.u64 %0, t; }" : "=r"(a) : "l"(p));
    return a;
}
__device__ __forceinline__ void cp16(uint32_t dst, const void* src) {
    asm volatile("cp.async.cg.shared.global [%0], [%1], 16;" :: "r"(dst), "l"(src));
}
#define CP_COMMIT() asm volatile("cp.async.commit_group;" ::: "memory")
#define CP_WAIT0()  asm volatile("cp.async.wait_group 0;" ::: "memory")

__device__ __forceinline__ void ldmx4(uint32_t* r, uint32_t a) {
    asm volatile("ldmatrix.sync.aligned.m8n8.x4.shared.b16 {%0,%1,%2,%3}, [%4];"
        : "=r"(r[0]), "=r"(r[1]), "=r"(r[2]), "=r"(r[3]) : "r"(a));
}
__device__ __forceinline__ void ldmx4t(uint32_t* r, uint32_t a) {
    asm volatile("ldmatrix.sync.aligned.m8n8.x4.trans.shared.b16 {%0,%1,%2,%3}, [%4];"
        : "=r"(r[0]), "=r"(r[1]), "=r"(r[2]), "=r"(r[3]) : "r"(a));
}
__device__ __forceinline__ void mma16816(
    float& c0, float& c1, float& c2, float& c3,
    uint32_t a0, uint32_t a1, uint32_t a2, uint32_t a3,
    uint32_t b0, uint32_t b1)
{
    asm volatile(
        "mma.sync.aligned.m16n8k16.row.col.f32.f16.f16.f32 "
        "{%0,%1,%2,%3}, {%4,%5,%6,%7}, {%8,%9}, {%0,%1,%2,%3};"
        : "+f"(c0), "+f"(c1), "+f"(c2), "+f"(c3)
        : "r"(a0), "r"(a1), "r"(a2), "r"(a3), "r"(b0), "r"(b1));
}
__device__ __forceinline__ uint32_t pack_h2(float a, float b) {
    __half2 t = __floats2half2_rn(a, b);
    return *(uint32_t*)&t;
}

// ---------------- LayerNorm (emits fp16 hi/lo) ----------------
__global__ void __launch_bounds__(256) ln_kernel(
    const float* __restrict__ x, const float* __restrict__ gamma,
    const float* __restrict__ beta, __half* __restrict__ xh,
    __half* __restrict__ xl)
{
    int row = blockIdx.x;
    int tid = threadIdx.x;
    const float* xr = x + (size_t)row * EE;
    float v0 = xr[tid], v1 = xr[tid+256], v2 = xr[tid+512];
    float s  = v0 + v1 + v2;
    float s2 = v0*v0 + v1*v1 + v2*v2;
    #pragma unroll
    for (int o = 16; o; o >>= 1) {
        s  += __shfl_xor_sync(0xffffffffu, s,  o);
        s2 += __shfl_xor_sync(0xffffffffu, s2, o);
    }
    __shared__ float sh0[8], sh1[8];
    int w = tid >> 5, l = tid & 31;
    if (l == 0) { sh0[w] = s; sh1[w] = s2; }
    __syncthreads();
    if (tid < 32) {
        s  = (l < 8) ? sh0[l] : 0.f;
        s2 = (l < 8) ? sh1[l] : 0.f;
        #pragma unroll
        for (int o = 4; o; o >>= 1) {
            s  += __shfl_xor_sync(0xffffffffu, s,  o);
            s2 += __shfl_xor_sync(0xffffffffu, s2, o);
        }
        if (l == 0) { sh0[0] = s; sh1[0] = s2; }
    }
    __syncthreads();
    s = sh0[0]; s2 = sh1[0];
    float mu   = s * (1.0f / EE);
    float var  = s2 * (1.0f / EE) - mu * mu;
    float rstd = rsqrtf(var + LN_EPS);
    size_t base = (size_t)row * EE;
    #pragma unroll
    for (int p = 0; p < 3; p++) {
        int c = tid + p * 256;
        float v = (p == 0) ? v0 : (p == 1) ? v1 : v2;
        float y = (v - mu) * rstd * gamma[c] + beta[c];
        __half h = __float2half_rn(y);
        xh[base + c] = h;
        xl[base + c] = __float2half_rn(y - __half2float(h));
    }
}

// ---------------- fp32 -> fp16 (hi only, for weights) ----------------
__global__ void __launch_bounds__(256) cvt_hi_kernel(
    const float* __restrict__ w, __half* __restrict__ hi, int n)
{
    int i = blockIdx.x * 256 + threadIdx.x;
    if (i < n) hi[i] = __float2half_rn(w[i]);
}

// ---------------- tensor GEMM, 2-pass: C = (Ah+Al)·Bh + bias ----------------
// 128x128 tile; BK=32; cp.async double-buffered; ldmatrix fragments.
#define GP 40
#define G_AR   (128*GP)
#define G_STG  (3*G_AR)
#define GEMM_SMEM (2*G_STG*2)
template<int EPI>
__global__ void __launch_bounds__(256, 2) mma_gemm(
    const __half* __restrict__ Ah, const __half* __restrict__ Al,
    const __half* __restrict__ Bh,
    const float* __restrict__ bias, float* __restrict__ C,
    __half* __restrict__ Pqh, __half* __restrict__ Pql,
    __half* __restrict__ Pkh, __half* __restrict__ Pvh,
    int N, int K)
{
    extern __shared__ __align__(16) __half gsm[];
    const uint32_t smb = smem_u32(gsm);

    const int tid  = threadIdx.x;
    const int lane = tid & 31;
    const int wid  = tid >> 5;
    const int wm   = (wid >> 2) * 64;
    const int wn   = (wid & 3) * 32;
    const int g    = lane >> 2;
    const int tg   = lane & 3;

    const int m0 = blockIdx.y * 128, n0 = blockIdx.x * 128;
    const int nchunks = K / 32;

    const int lr = tid >> 1;
    const int lu = (tid & 1) * 16;
    const __half* pah = Ah + (size_t)(m0 + lr) * K + lu;
    const __half* pal = Al + (size_t)(m0 + lr) * K + lu;
    const __half* pbh = Bh + (size_t)(n0 + lr) * K + lu;
    const uint32_t drow = smb + (lr * GP + lu) * 2;

    auto stage = [&](int c, int s) {
        uint32_t d = drow + s * (G_STG * 2);
        const __half* a;
        a = pah + c * 32; cp16(d, a);              cp16(d + 16, a + 8);
        a = pal + c * 32; cp16(d + G_AR*2, a);     cp16(d + G_AR*2 + 16, a + 8);
        a = pbh + c * 32; cp16(d + 2*G_AR*2, a);   cp16(d + 2*G_AR*2 + 16, a + 8);
    };

    float acc[4][4][4] = {};

    stage(0, 0);
    CP_COMMIT();

    for (int c = 0; c < nchunks; c++) {
        CP_WAIT0();
        __syncthreads();
        if (c + 1 < nchunks) { stage(c + 1, (c + 1) & 1); CP_COMMIT(); }

        const uint32_t stb = smb + (c & 1) * (G_STG * 2);
        #pragma unroll
        for (int ks = 0; ks < 2; ks++) {
            const int kb = ks * 16;
            uint32_t ah[4][4], al[4][4], bh[4][2];
            {
                const int arow = (lane & 15);
                const int acol = kb + (lane >> 4) * 8;
                #pragma unroll
                for (int mt = 0; mt < 4; mt++) {
                    uint32_t a = stb + ((wm + mt * 16 + arow) * GP + acol) * 2;
                    ldmx4(ah[mt], a);
                    ldmx4(al[mt], a + G_AR * 2);
                }
            }
            {
                const int brow = (lane & 7) + (lane >> 4) * 8;
                const int bcol = kb + ((lane >> 3) & 1) * 8;
                #pragma unroll
                for (int p = 0; p < 2; p++) {
                    uint32_t a = stb + (2 * G_AR + (wn + p * 16 + brow) * GP + bcol) * 2;
                    uint32_t t[4];
                    ldmx4(t, a);
                    bh[2*p][0] = t[0]; bh[2*p][1] = t[1];
                    bh[2*p+1][0] = t[2]; bh[2*p+1][1] = t[3];
                }
            }
            #pragma unroll
            for (int mt = 0; mt < 4; mt++)
                #pragma unroll
                for (int nt = 0; nt < 4; nt++)
                    mma16816(acc[mt][nt][0], acc[mt][nt][1], acc[mt][nt][2], acc[mt][nt][3],
                             ah[mt][0], ah[mt][1], ah[mt][2], ah[mt][3],
                             bh[nt][0], bh[nt][1]);
            #pragma unroll
            for (int mt = 0; mt < 4; mt++)
                #pragma unroll
                for (int nt = 0; nt < 4; nt++)
                    mma16816(acc[mt][nt][0], acc[mt][nt][1], acc[mt][nt][2], acc[mt][nt][3],
                             al[mt][0], al[mt][1], al[mt][2], al[mt][3],
                             bh[nt][0], bh[nt][1]);
        }
        __syncthreads();
    }

    #pragma unroll
    for (int mt = 0; mt < 4; mt++) {
        #pragma unroll
        for (int half = 0; half < 2; half++) {
            int m = m0 + wm + mt * 16 + g + half * 8;
            int b_ = m >> 11;
            int s_ = m & 2047;
            #pragma unroll
            for (int nt = 0; nt < 4; nt++) {
                int n = n0 + wn + nt * 8 + 2 * tg;
                float e0 = acc[mt][nt][half*2 + 0] + __ldg(&bias[n]);
                float e1 = acc[mt][nt][half*2 + 1] + __ldg(&bias[n + 1]);
                if (EPI == 1) {
                    *(float2*)&C[(size_t)m * N + n] = make_float2(e0, e1);
                } else {
                    int h_ = n / 192;
                    int rem = n - h_ * 192;
                    int which = rem >> 6;
                    int d0 = rem & 63;
                    size_t base = ((size_t)(b_ * HH + h_) * SS + s_) * HD + d0;
                    uint32_t h2 = pack_h2(e0, e1);
                    if (which == 0) {
                        __half2 hv = *(__half2*)&h2;
                        uint32_t l2 = pack_h2(e0 - __low2float(hv), e1 - __high2float(hv));
                        *(uint32_t*)&Pqh[base] = h2;
                        *(uint32_t*)&Pql[base] = l2;
                    } else if (which == 1) {
                        *(uint32_t*)&Pkh[base] = h2;
                    } else {
                        *(uint32_t*)&Pvh[base] = h2;
                    }
                }
            }
        }
    }
}

// ---------------- Flash attention: QK 2-pass (Qh+Ql)·Kh, PV 1-pass Ph·Vh ----------------
#define AP 72
#define A_QOFF  (128*AP)          // halves
#define A_KV0   (2*A_QOFF)
#define A_KVSTG (2*64*AP)         // {Kh, Vh} per stage
#define ATT_SMEM ((A_KV0 + 2*A_KVSTG) * 2)   // 73728 bytes
__global__ void __launch_bounds__(256) attn_mma(
    const __half* __restrict__ qh, const __half* __restrict__ ql,
    const __half* __restrict__ kh, const __half* __restrict__ vh,
    __half* __restrict__ Oh, __half* __restrict__ Ol)
{
    extern __shared__ __align__(16) __half asm_[];
    const uint32_t smb = smem_u32(asm_);

    const int tid  = threadIdx.x;
    const int lane = tid & 31;
    const int wid  = tid >> 5;
    const int g    = lane >> 2;
    const int tg   = lane & 3;
    const int wm   = wid * 16;

    const int bh = blockIdx.y;
    const int b_ = bh / HH;
    const int h_ = bh - b_ * HH;
    const size_t headoff = (size_t)bh * SS * HD;

    // ---- Q staging ----
    {
        int row = tid & 127;
        const __half* src = ((tid < 128) ? qh : ql) + headoff
                          + (size_t)(blockIdx.x * 128 + row) * HD;
        uint32_t dst = smb + (((tid < 128) ? 0 : A_QOFF) + row * AP) * 2;
        #pragma unroll
        for (int u = 0; u < 8; u++)
            cp16(dst + u * 16, src + u * 8);
    }
    // ---- KV staging: sel 0=Kh, 1=Vh (128 active threads) ----
    const int sel = tid >> 6;
    const int krow = tid & 63;
    const __half* ksrc = ((sel == 0) ? kh : vh) + headoff + (size_t)krow * HD;
    const uint32_t kdst = smb + (A_KV0 + sel * (64*AP) + krow * AP) * 2;

    auto stageKV = [&](int kt, int s) {
        if (sel < 2) {
            const __half* src = ksrc + (size_t)(kt * 64) * HD;
            uint32_t dst = kdst + s * (A_KVSTG * 2);
            #pragma unroll
            for (int u = 0; u < 8; u++)
                cp16(dst + u * 16, src + u * 8);
        }
    };

    stageKV(0, 0);
    CP_COMMIT();

    float oacc[8][4] = {};
    float m0_ = -1e30f, m1_ = -1e30f, l0_ = 0.f, l1_ = 0.f;
    const float sc = 0.125f;

    for (int kt = 0; kt < SS / 64; kt++) {
        CP_WAIT0();
        __syncthreads();
        if (kt + 1 < SS / 64) { stageKV(kt + 1, (kt + 1) & 1); CP_COMMIT(); }

        const uint32_t kvb = smb + (A_KV0 + (kt & 1) * A_KVSTG) * 2;

        // ---- S = (Qh+Ql) Kh^T ----
        float sacc[8][4] = {};
        #pragma unroll
        for (int kc = 0; kc < 4; kc++) {
            const int kb = kc * 16;
            uint32_t aqh[4], aql[4], bk[8][2];
            {
                int row = wm + (lane & 15);
                int col = kb + (lane >> 4) * 8;
                uint32_t a = smb + (row * AP + col) * 2;
                ldmx4(aqh, a);
                ldmx4(aql, a + A_QOFF * 2);
            }
            const int brow = (lane & 7) + (lane >> 4) * 8;
            const int bcol = kb + ((lane >> 3) & 1) * 8;
            #pragma unroll
            for (int p = 0; p < 4; p++) {
                uint32_t t[4];
                ldmx4(t, kvb + ((p * 16 + brow) * AP + bcol) * 2);
                bk[2*p][0] = t[0]; bk[2*p][1] = t[1];
                bk[2*p+1][0] = t[2]; bk[2*p+1][1] = t[3];
            }
            #pragma unroll
            for (int nt = 0; nt < 8; nt++)
                mma16816(sacc[nt][0], sacc[nt][1], sacc[nt][2], sacc[nt][3],
                         aqh[0], aqh[1], aqh[2], aqh[3], bk[nt][0], bk[nt][1]);
            #pragma unroll
            for (int nt = 0; nt < 8; nt++)
                mma16816(sacc[nt][0], sacc[nt][1], sacc[nt][2], sacc[nt][3],
                         aql[0], aql[1], aql[2], aql[3], bk[nt][0], bk[nt][1]);
        }

        // ---- online softmax ----
        float rm0 = -1e30f, rm1 = -1e30f;
        #pragma unroll
        for (int nt = 0; nt < 8; nt++) {
            rm0 = fmaxf(rm0, fmaxf(sacc[nt][0], sacc[nt][1]));
            rm1 = fmaxf(rm1, fmaxf(sacc[nt][2], sacc[nt][3]));
        }
        rm0 *= sc; rm1 *= sc;
        rm0 = fmaxf(rm0, __shfl_xor_sync(0xffffffffu, rm0, 1));
        rm0 = fmaxf(rm0, __shfl_xor_sync(0xffffffffu, rm0, 2));
        rm1 = fmaxf(rm1, __shfl_xor_sync(0xffffffffu, rm1, 1));
        rm1 = fmaxf(rm1, __shfl_xor_sync(0xffffffffu, rm1, 2));
        float mn0 = fmaxf(m0_, rm0), mn1 = fmaxf(m1_, rm1);
        float rs0 = 0.f, rs1 = 0.f;
        #pragma unroll
        for (int nt = 0; nt < 8; nt++) {
            sacc[nt][0] = __expf(sacc[nt][0] * sc - mn0);
            sacc[nt][1] = __expf(sacc[nt][1] * sc - mn0);
            sacc[nt][2] = __expf(sacc[nt][2] * sc - mn1);
            sacc[nt][3] = __expf(sacc[nt][3] * sc - mn1);
            rs0 += sacc[nt][0] + sacc[nt][1];
            rs1 += sacc[nt][2] + sacc[nt][3];
        }
        rs0 += __shfl_xor_sync(0xffffffffu, rs0, 1);
        rs0 += __shfl_xor_sync(0xffffffffu, rs0, 2);
        rs1 += __shfl_xor_sync(0xffffffffu, rs1, 1);
        rs1 += __shfl_xor_sync(0xffffffffu, rs1, 2);
        float al0 = __expf(m0_ - mn0), al1 = __expf(m1_ - mn1);
        l0_ = l0_ * al0 + rs0;  m0_ = mn0;
        l1_ = l1_ * al1 + rs1;  m1_ = mn1;
        #pragma unroll
        for (int nt = 0; nt < 8; nt++) {
            oacc[nt][0] *= al0; oacc[nt][1] *= al0;
            oacc[nt][2] *= al1; oacc[nt][3] *= al1;
        }

        // ---- pack P (hi only) ----
        uint32_t ph[4][4];
        #pragma unroll
        for (int kc = 0; kc < 4; kc++) {
            ph[kc][0] = pack_h2(sacc[2*kc][0],   sacc[2*kc][1]);
            ph[kc][1] = pack_h2(sacc[2*kc][2],   sacc[2*kc][3]);
            ph[kc][2] = pack_h2(sacc[2*kc+1][0], sacc[2*kc+1][1]);
            ph[kc][3] = pack_h2(sacc[2*kc+1][2], sacc[2*kc+1][3]);
        }

        // ---- O += Ph Vh, V via ldmatrix.trans ----
        #pragma unroll
        for (int kc = 0; kc < 4; kc++) {
            const int kb = kc * 16;
            uint32_t bv[8][2];
            const int vrow = kb + ((lane >> 3) & 1) * 8 + (lane & 7);
            const int vcol = (lane >> 4) * 8;
            #pragma unroll
            for (int p = 0; p < 4; p++) {
                uint32_t t[4];
                ldmx4t(t, kvb + (64*AP + vrow * AP + p * 16 + vcol) * 2);
                bv[2*p][0] = t[0]; bv[2*p][1] = t[1];
                bv[2*p+1][0] = t[2]; bv[2*p+1][1] = t[3];
            }
            #pragma unroll
            for (int nt = 0; nt < 8; nt++)
                mma16816(oacc[nt][0], oacc[nt][1], oacc[nt][2], oacc[nt][3],
                         ph[kc][0], ph[kc][1], ph[kc][2], ph[kc][3], bv[nt][0], bv[nt][1]);
        }
        __syncthreads();
    }

    // ---- epilogue ----
    float inv0 = 1.0f / l0_, inv1 = 1.0f / l1_;
    int sbase = blockIdx.x * 128 + wm;
    size_t ob0 = ((size_t)(b_ * SS + sbase + g))     * EE + h_ * HD + 2 * tg;
    size_t ob1 = ((size_t)(b_ * SS + sbase + g + 8)) * EE + h_ * HD + 2 * tg;
    #pragma unroll
    for (int nt = 0; nt < 8; nt++) {
        int d = nt * 8;
        float e0 = oacc[nt][0] * inv0, e1 = oacc[nt][1] * inv0;
        uint32_t h2 = pack_h2(e0, e1);
        __half2 hv = *(__half2*)&h2;
        uint32_t l2 = pack_h2(e0 - __low2float(hv), e1 - __high2float(hv));
        *(uint32_t*)&Oh[ob0 + d] = h2;
        *(uint32_t*)&Ol[ob0 + d] = l2;
        e0 = oacc[nt][2] * inv1; e1 = oacc[nt][3] * inv1;
        h2 = pack_h2(e0, e1);
        hv = *(__half2*)&h2;
        l2 = pack_h2(e0 - __low2float(hv), e1 - __high2float(hv));
        *(uint32_t*)&Oh[ob1 + d] = h2;
        *(uint32_t*)&Ol[ob1 + d] = l2;
    }
}

// ---------------- launch ----------------
extern "C" void kernel_launch(void* const* d_in, const int* in_sizes, int n_in,
                              void* d_out, int out_size)
{
    const float* x     = (const float*)d_in[0];
    const float* gamma = (const float*)d_in[1];
    const float* beta  = (const float*)d_in[2];
    const float* Wqkv  = (const float*)d_in[3];
    const float* bqkv  = (const float*)d_in[4];
    const float* Wo    = (const float*)d_in[5];
    const float* bo    = (const float*)d_in[6];
    float* out = (float*)d_out;

    __half *xh, *xl, *wqh, *woh, *oh, *ol;
    __half *qh, *ql, *kh, *vh;
    cudaGetSymbolAddress((void**)&xh,  g_xh);
    cudaGetSymbolAddress((void**)&xl,  g_xl);
    cudaGetSymbolAddress((void**)&wqh, g_wqh);
    cudaGetSymbolAddress((void**)&woh, g_woh);
    cudaGetSymbolAddress((void**)&qh,  g_qh);
    cudaGetSymbolAddress((void**)&ql,  g_ql);
    cudaGetSymbolAddress((void**)&kh,  g_kh);
    cudaGetSymbolAddress((void**)&vh,  g_vh);
    cudaGetSymbolAddress((void**)&oh,  g_oh);
    cudaGetSymbolAddress((void**)&ol,  g_ol);

    cudaFuncSetAttribute(attn_mma,    cudaFuncAttributeMaxDynamicSharedMemorySize, ATT_SMEM);
    cudaFuncSetAttribute(mma_gemm<0>, cudaFuncAttributeMaxDynamicSharedMemorySize, GEMM_SMEM);
    cudaFuncSetAttribute(mma_gemm<1>, cudaFuncAttributeMaxDynamicSharedMemorySize, GEMM_SMEM);

    ln_kernel<<<MROWS, 256>>>(x, gamma, beta, xh, xl);
    cvt_hi_kernel<<<(NQKV*EE + 255)/256, 256>>>(Wqkv, wqh, NQKV*EE);
    cvt_hi_kernel<<<(EE*EE   + 255)/256, 256>>>(Wo,   woh, EE*EE);

    mma_gemm<0><<<dim3(NQKV/128, MROWS/128), 256, GEMM_SMEM>>>(
        xh, xl, wqh, bqkv, nullptr, qh, ql, kh, vh, NQKV, EE);

    attn_mma<<<dim3(SS/128, BB*HH), 256, ATT_SMEM>>>(qh, ql, kh, vh, oh, ol);

    mma_gemm<1><<<dim3(EE/128, MROWS/128), 256, GEMM_SMEM>>>(
        oh, ol, woh, bo, out, nullptr, nullptr, nullptr, nullptr, EE, EE);
}